// round 9
// baseline (speedup 1.0000x reference)
#include <cuda_runtime.h>
#include <cuda_bf16.h>
#include <math.h>
#include <stdint.h>

#define N_NODES 8192
#define D 64
#define NT 8192
#define KC 192            // packed K: [hi | lo | hi] / [hi | hi | lo]
#define EMAX 262144

// ---------------- scratch (no allocations allowed) ----------------
// Invariant: g_deg and g_agg are ZERO at entry to kernel_launch (zero-init at
// load; re-zeroed by the GEMM's idle lower-triangle CTAs every call).
__device__ float g_deg[N_NODES];
__device__ float g_h[N_NODES * D];     // x @ W
__device__ float g_agg[N_NODES * D];   // neighbor-sum (excl. self term)
__device__ __nv_bfloat16 g_A2[N_NODES * KC];
__device__ __nv_bfloat16 g_B2[N_NODES * KC];

struct Cls {
    const float* x;
    const void*  ei;
    const float* W;
    const float* b;
    int E;
    int ei32;
};

// Published by launch 0 (block 0) for later launches.
__device__ const float* gp_x;
__device__ const void*  gp_ei;
__device__ const float* gp_W;
__device__ const float* gp_b;
__device__ int          g_E;
__device__ int          g_ei32;

// Cheap content test: 8 independent samples. float32 N(0,1) bit patterns can
// never read back as integers in [0, N_NODES) for all samples.
__device__ __forceinline__ bool rok64(const long long* p, int n) {
    int st = n >> 3;
    long long v[8];
#pragma unroll
    for (int k = 0; k < 8; k++) v[k] = p[k * st];
    bool ok = true;
#pragma unroll
    for (int k = 0; k < 8; k++) ok &= (v[k] >= 0 && v[k] < N_NODES);
    return ok;
}
__device__ __forceinline__ bool rok32(const int* p, int n) {
    int st = n >> 3;
    int v[8];
#pragma unroll
    for (int k = 0; k < 8; k++) v[k] = p[k * st];
    bool ok = true;
#pragma unroll
    for (int k = 0; k < 8; k++) ok &= (v[k] >= 0 && v[k] < N_NODES);
    return ok;
}

__device__ Cls do_classify(const void* p0, const void* p1, const void* p2, const void* p3,
                           int s0, int s1, int s2, int s3) {
    Cls c; c.x = nullptr; c.ei = nullptr; c.W = nullptr; c.b = nullptr; c.E = 0; c.ei32 = 1;
    const void* ps[4] = {p0, p1, p2, p3};
    int ss[4] = {s0, s1, s2, s3};
    int big[2]; int nb = 0;
#pragma unroll
    for (int j = 0; j < 4; j++) {
        if (ss[j] == D) c.b = (const float*)ps[j];
        else if (ss[j] == D * D) c.W = (const float*)ps[j];
        else if (nb < 2) big[nb++] = j;
    }
#pragma unroll
    for (int k = 0; k < 2; k++) {
        const void* cand = ps[big[k]];
        int n = ss[big[k]];
        const void* other = ps[big[1 - k]];
        if (rok64((const long long*)cand, n)) {
            c.ei = cand; c.ei32 = 0; c.E = n / 2; c.x = (const float*)other; return c;
        }
        if (rok32((const int*)cand, n)) {
            c.ei = cand; c.ei32 = 1; c.E = n / 2; c.x = (const float*)other; return c;
        }
    }
    c.ei = ps[big[1]]; c.ei32 = 1; c.E = ss[big[1]] / 2;
    c.x = (const float*)ps[big[0]];
    return c;
}

__device__ __forceinline__ int fetch_idx(const void* ei, int i, int ei32) {
    if (ei32) return ((const int*)ei)[i];
    return (int)((const long long*)ei)[i];
}

__device__ __forceinline__ uint32_t smem_u32(const void* p) {
    uint32_t a;
    asm("{ .reg .u64 t; cvta.to.shared.u64 t, %1; cvt.u32.u64 %0, t; }" : "=r"(a) : "l"(p));
    return a;
}

// ---- launch 0: classify+publish, degree count (blocks 0..1023), x@W (1024..3071) ----
__global__ void k_deg_xw(const void* p0, const void* p1, const void* p2, const void* p3,
                         int s0, int s1, int s2, int s3) {
    __shared__ float sW[D * D];
    Cls c = do_classify(p0, p1, p2, p3, s0, s1, s2, s3);
    int blk = blockIdx.x, tid = threadIdx.x;
    if (blk == 0 && tid == 0) {   // publish for later launches
        gp_x = c.x; gp_ei = c.ei; gp_W = c.W; gp_b = c.b; g_E = c.E; g_ei32 = c.ei32;
        __threadfence();
    }
    if (blk < 1024) {
        int e = blk * 256 + tid;
        if (e < c.E && e < EMAX) {
            int dst = fetch_idx(c.ei, c.E + e, c.ei32);
            if ((unsigned)dst < (unsigned)N_NODES) atomicAdd(&g_deg[dst], 1.0f);
        }
        return;
    }
    for (int i = tid; i < D * D; i += 256) sW[i] = c.W[i];
    __syncthreads();
    int row = (blk - 1024) * 4 + (tid >> 6);
    int col = tid & 63;
    const float* xr = c.x + row * D;
    float acc = 0.0f;
#pragma unroll
    for (int k = 0; k < D; k++) acc += xr[k] * sW[k * D + col];
    g_h[row * D + col] = acc;
}

// ---- launch 1: edge scatter (warp per edge) into zeroed g_agg ----
__global__ void k_scatter() {
    const void* ei = gp_ei;
    int E = g_E, ei32 = g_ei32;
    int gw = (blockIdx.x * blockDim.x + threadIdx.x) >> 5;
    int lane = threadIdx.x & 31;
    if (gw >= E || gw >= EMAX) return;
    int src = fetch_idx(ei, gw, ei32);
    int dst = fetch_idx(ei, E + gw, ei32);
    if ((unsigned)src >= (unsigned)N_NODES) return;
    if ((unsigned)dst >= (unsigned)N_NODES) return;
    float norm = rsqrtf(g_deg[src] + 1.0f) * rsqrtf(g_deg[dst] + 1.0f);  // +1 self-loop
    float2 v = ((const float2*)(g_h + src * D))[lane];
    atomicAdd(&g_agg[dst * D + lane * 2],     norm * v.x);
    atomicAdd(&g_agg[dst * D + lane * 2 + 1], norm * v.y);
}

// ---- launch 2: self-term + bias + relu + bf16 hi/lo split-pack ----
__global__ void k_pack() {
    const float* __restrict__ b = gp_b;
    int idx = blockIdx.x * blockDim.x + threadIdx.x;
    if (idx >= N_NODES * D) return;
    int row = idx >> 6, col = idx & 63;
    float self = g_h[idx] / (g_deg[row] + 1.0f);   // dinv^2 * h
    float v = g_agg[idx] + self + b[col];
    v = v > 0.0f ? v : 0.0f;
    __nv_bfloat16 hi = __float2bfloat16(v);
    __nv_bfloat16 lo = __float2bfloat16(v - __bfloat162float(hi));
    __nv_bfloat16* a2 = g_A2 + row * KC;
    __nv_bfloat16* b2 = g_B2 + row * KC;
    a2[col] = hi; a2[col + 64] = lo; a2[col + 128] = hi;
    b2[col] = hi; b2[col + 64] = hi; b2[col + 128] = lo;
}

// ---- launch 3: C = A2 @ B2^T via mma.sync bf16, symmetric upper-tri tiles ----
#define ROW_BYTES (KC * 2)                  // 384
#define TILE_BYTES (128 * ROW_BYTES)        // 49152
#define SMEM_TOTAL (2 * TILE_BYTES)         // 98304
#define TSTRIDE 132
#define CLEAN_CTAS 2016
#define CLEAN_WORDS (N_NODES * D + N_NODES)
#define WORDS_PER_CTA ((CLEAN_WORDS + CLEAN_CTAS - 1) / CLEAN_CTAS)

__device__ __forceinline__ uint32_t sw_off(int row, int chunk) {
    return (uint32_t)(row * ROW_BYTES + (((chunk & 24) | ((chunk & 7) ^ (row & 7))) << 4));
}

#define LDSM_X4(r0, r1, r2, r3, a) \
    asm volatile("ldmatrix.sync.aligned.m8n8.x4.shared.b16 {%0,%1,%2,%3}, [%4];" \
        : "=r"(r0), "=r"(r1), "=r"(r2), "=r"(r3) : "r"(a))

#define MMA_16816(d, a, b) \
    asm volatile("mma.sync.aligned.m16n8k16.row.col.f32.bf16.bf16.f32 " \
        "{%0,%1,%2,%3}, {%4,%5,%6,%7}, {%8,%9}, {%0,%1,%2,%3};" \
        : "+f"((d)[0]), "+f"((d)[1]), "+f"((d)[2]), "+f"((d)[3]) \
        : "r"((a)[0]), "r"((a)[1]), "r"((a)[2]), "r"((a)[3]), "r"((b)[0]), "r"((b)[1]))

#define CP_ASYNC_16(smem_addr, gptr) \
    asm volatile("cp.async.cg.shared.global [%0], [%1], 16;" :: "r"(smem_addr), "l"(gptr) : "memory")

__global__ void __launch_bounds__(256, 2) k_gemm_mma(float* __restrict__ C) {
    int bi = blockIdx.y, bj = blockIdx.x;
    int tid = threadIdx.x;

    if (bj < bi) {
        // idle lower-triangle CTA: re-zero g_agg/g_deg for the next graph replay
        int cid = bi * (bi - 1) / 2 + bj;
        int w0 = cid * WORDS_PER_CTA;
        for (int k = tid; k < WORDS_PER_CTA; k += 256) {
            int w = w0 + k;
            if (w < N_NODES * D) g_agg[w] = 0.0f;
            else if (w < CLEAN_WORDS) g_deg[w - N_NODES * D] = 0.0f;
        }
        return;
    }

    extern __shared__ char smem[];
    char* sA = smem;
    char* sB = smem + TILE_BYTES;
    uint32_t sA_u = smem_u32(sA);
    uint32_t sB_u = smem_u32(sB);

    int wid = tid >> 5, lane = tid & 31;
    int warp_m = wid >> 1;
    int warp_n = wid & 1;

    const char* gA = (const char*)(g_A2 + bi * 128 * KC);
    const char* gB = (const char*)(g_B2 + bj * 128 * KC);

    // Two commit groups by K-half (chunks 0-11, 12-23).
#pragma unroll
    for (int h = 0; h < 2; h++) {
#pragma unroll
        for (int it = 0; it < 6; it++) {
            int q = it * 256 + tid;               // 0..1535
            int row = q / 12, chunk = h * 12 + q % 12;
            uint32_t off = sw_off(row, chunk);
            CP_ASYNC_16(sA_u + off, gA + row * ROW_BYTES + chunk * 16);
            CP_ASYNC_16(sB_u + off, gB + row * ROW_BYTES + chunk * 16);
        }
        asm volatile("cp.async.commit_group;" ::: "memory");
    }

    int a_row_in16 = (lane & 7) | (lane & 8);
    int a_csub = lane >> 4;
    int b_row_in16 = (lane & 7) | ((lane >> 1) & 8);
    int b_csub = (lane >> 3) & 1;
    // precompute per-thread smem byte offsets (row*ROW_BYTES part is fixed)
    int a_row0 = warp_m * 32 + a_row_in16;        // +16 for mi=1
    int b_row0 = warp_n * 64 + b_row_in16;        // +16*nt

    float acc[2][8][4];
#pragma unroll
    for (int mi = 0; mi < 2; mi++)
#pragma unroll
        for (int ni = 0; ni < 8; ni++)
#pragma unroll
            for (int v = 0; v < 4; v++) acc[mi][ni][v] = 0.0f;

    uint32_t a_cur[2][4], b_cur[4][4];
    uint32_t a_nxt[2][4], b_nxt[4][4];

    // half 0 landed (1 group still pending)
    asm volatile("cp.async.wait_group 1;" ::: "memory");
    __syncthreads();

    // prologue: fragments for s=0
#pragma unroll
    for (int mi = 0; mi < 2; mi++)
        LDSM_X4(a_cur[mi][0], a_cur[mi][1], a_cur[mi][2], a_cur[mi][3],
                sA_u + sw_off(a_row0 + mi * 16, a_csub));
#pragma unroll
    for (int nt = 0; nt < 4; nt++)
        LDSM_X4(b_cur[nt][0], b_cur[nt][1], b_cur[nt][2], b_cur[nt][3],
                sB_u + sw_off(b_row0 + nt * 16, b_csub));

#pragma unroll
    for (int s = 0; s < 12; s++) {
        if (s == 5) {   // half 1 must be resident before prefetching s=6 fragments
            asm volatile("cp.async.wait_group 0;" ::: "memory");
            __syncthreads();
        }
        if (s < 11) {
            int kc = (s + 1) * 2;
#pragma unroll
            for (int mi = 0; mi < 2; mi++)
                LDSM_X4(a_nxt[mi][0], a_nxt[mi][1], a_nxt[mi][2], a_nxt[mi][3],
                        sA_u + sw_off(a_row0 + mi * 16, kc + a_csub));
#pragma unroll
            for (int nt = 0; nt < 4; nt++)
                LDSM_X4(b_nxt[nt][0], b_nxt[nt][1], b_nxt[nt][2], b_nxt[nt][3],
                        sB_u + sw_off(b_row0 + nt * 16, kc + b_csub));
        }

#pragma unroll
        for (int mi = 0; mi < 2; mi++)
#pragma unroll
            for (int ni = 0; ni < 8; ni++) {
                uint32_t bb[2];
                bb[0] = b_cur[ni >> 1][(ni & 1) * 2];
                bb[1] = b_cur[ni >> 1][(ni & 1) * 2 + 1];
                MMA_16816(acc[mi][ni], a_cur[mi], bb);
            }

        // register rename under full unroll
#pragma unroll
        for (int mi = 0; mi < 2; mi++)
#pragma unroll
            for (int v = 0; v < 4; v++) a_cur[mi][v] = a_nxt[mi][v];
#pragma unroll
        for (int nt = 0; nt < 4; nt++)
#pragma unroll
            for (int v = 0; v < 4; v++) b_cur[nt][v] = b_nxt[nt][v];
    }

    // ---- epilogue 1: direct store of C[bi, bj] ----
    int gr = lane >> 2, gc = (lane & 3) * 2;
#pragma unroll
    for (int mi = 0; mi < 2; mi++) {
        int row0 = bi * 128 + warp_m * 32 + mi * 16 + gr;
#pragma unroll
        for (int ni = 0; ni < 8; ni++) {
            int col = bj * 128 + warp_n * 64 + ni * 8 + gc;
            float* pp0 = C + (long long)row0 * NT + col;
            float* pp1 = pp0 + 8LL * NT;
            *(float2*)pp0 = make_float2(acc[mi][ni][0], acc[mi][ni][1]);
            *(float2*)pp1 = make_float2(acc[mi][ni][2], acc[mi][ni][3]);
        }
    }

    // ---- epilogue 2: transposed store of C[bj, bi] via smem staging ----
    if (bi == bj) return;
    __syncthreads();
    float* sT = (float*)smem;
#pragma unroll
    for (int mi = 0; mi < 2; mi++) {
        int lr = warp_m * 32 + mi * 16 + gr;
#pragma unroll
        for (int ni = 0; ni < 8; ni++) {
            int lc = warp_n * 64 + ni * 8 + gc;
            sT[lc * TSTRIDE + lr]           = acc[mi][ni][0];
            sT[(lc + 1) * TSTRIDE + lr]     = acc[mi][ni][1];
            sT[lc * TSTRIDE + lr + 8]       = acc[mi][ni][2];
            sT[(lc + 1) * TSTRIDE + lr + 8] = acc[mi][ni][3];
        }
    }
    __syncthreads();
    int half = tid >> 7;
    int r = tid & 127;
    const float* srow = sT + r * TSTRIDE + half * 64;
    float* drow = C + (long long)(bj * 128 + r) * NT + bi * 128 + half * 64;
#pragma unroll
    for (int k = 0; k < 16; k++) {
        float4 v = *(const float4*)(srow + k * 4);
        *(float4*)(drow + k * 4) = v;
    }
}

extern "C" void kernel_launch(void* const* d_in, const int* in_sizes, int n_in,
                              void* d_out, int out_size) {
    float* out = (float*)d_out;

    const void* p0 = n_in > 0 ? d_in[0] : nullptr;
    const void* p1 = n_in > 1 ? d_in[1] : nullptr;
    const void* p2 = n_in > 2 ? d_in[2] : nullptr;
    const void* p3 = n_in > 3 ? d_in[3] : nullptr;
    int s0 = n_in > 0 ? in_sizes[0] : 0;
    int s1 = n_in > 1 ? in_sizes[1] : 0;
    int s2 = n_in > 2 ? in_sizes[2] : 0;
    int s3 = n_in > 3 ? in_sizes[3] : 0;

    static bool attr_set = false;
    if (!attr_set) {
        cudaFuncSetAttribute(k_gemm_mma, cudaFuncAttributeMaxDynamicSharedMemorySize, SMEM_TOTAL);
        attr_set = true;
    }

    // launch 0: classify/publish + degree count + x@W
    k_deg_xw<<<3072, 256>>>(p0, p1, p2, p3, s0, s1, s2, s3);
    // launch 1: edge scatter, warp per edge
    k_scatter<<<(EMAX + 7) / 8, 256>>>();
    // launch 2: self term + bias + relu + split-pack
    k_pack<<<(N_NODES * D + 255) / 256, 256>>>();
    // launch 3: GEMM (ncu captures this index)
    dim3 grid(NT / 128, NT / 128);
    k_gemm_mma<<<grid, 256, SMEM_TOTAL>>>(out);
}

// round 10
// speedup vs baseline: 1.1113x; 1.1113x over previous
#include <cuda_runtime.h>
#include <cuda_fp16.h>
#include <math.h>
#include <stdint.h>

#define N_NODES 8192
#define D 64
#define NT 8192
#define EMAX 262144

// ---------------- scratch (no allocations allowed) ----------------
// Invariant: g_deg and g_agg are ZERO at entry (zero-init at load; re-zeroed
// by the GEMM's idle lower-triangle CTAs every call).
__device__ float g_deg[N_NODES];
__device__ float g_h[N_NODES * D];     // x @ W
__device__ float g_agg[N_NODES * D];   // neighbor-sum (excl. self term)
__device__ __half g_P[N_NODES * D];    // fp16(relu(gcn)) — both GEMM operands

struct Cls {
    const float* x;
    const void*  ei;
    const float* W;
    const float* b;
    int E;
    int ei32;
};

// Published by launch 0 (block 0) for later launches.
__device__ const float* gp_x;
__device__ const void*  gp_ei;
__device__ const float* gp_W;
__device__ const float* gp_b;
__device__ int          g_E;
__device__ int          g_ei32;

__device__ __forceinline__ bool rok64(const long long* p, int n) {
    int st = n >> 3;
    long long v[8];
#pragma unroll
    for (int k = 0; k < 8; k++) v[k] = p[k * st];
    bool ok = true;
#pragma unroll
    for (int k = 0; k < 8; k++) ok &= (v[k] >= 0 && v[k] < N_NODES);
    return ok;
}
__device__ __forceinline__ bool rok32(const int* p, int n) {
    int st = n >> 3;
    int v[8];
#pragma unroll
    for (int k = 0; k < 8; k++) v[k] = p[k * st];
    bool ok = true;
#pragma unroll
    for (int k = 0; k < 8; k++) ok &= (v[k] >= 0 && v[k] < N_NODES);
    return ok;
}

__device__ Cls do_classify(const void* p0, const void* p1, const void* p2, const void* p3,
                           int s0, int s1, int s2, int s3) {
    Cls c; c.x = nullptr; c.ei = nullptr; c.W = nullptr; c.b = nullptr; c.E = 0; c.ei32 = 1;
    const void* ps[4] = {p0, p1, p2, p3};
    int ss[4] = {s0, s1, s2, s3};
    int big[2]; int nb = 0;
#pragma unroll
    for (int j = 0; j < 4; j++) {
        if (ss[j] == D) c.b = (const float*)ps[j];
        else if (ss[j] == D * D) c.W = (const float*)ps[j];
        else if (nb < 2) big[nb++] = j;
    }
#pragma unroll
    for (int k = 0; k < 2; k++) {
        const void* cand = ps[big[k]];
        int n = ss[big[k]];
        const void* other = ps[big[1 - k]];
        if (rok64((const long long*)cand, n)) {
            c.ei = cand; c.ei32 = 0; c.E = n / 2; c.x = (const float*)other; return c;
        }
        if (rok32((const int*)cand, n)) {
            c.ei = cand; c.ei32 = 1; c.E = n / 2; c.x = (const float*)other; return c;
        }
    }
    c.ei = ps[big[1]]; c.ei32 = 1; c.E = ss[big[1]] / 2;
    c.x = (const float*)ps[big[0]];
    return c;
}

__device__ __forceinline__ int fetch_idx(const void* ei, int i, int ei32) {
    if (ei32) return ((const int*)ei)[i];
    return (int)((const long long*)ei)[i];
}

__device__ __forceinline__ uint32_t smem_u32(const void* p) {
    uint32_t a;
    asm("{ .reg .u64 t; cvta.to.shared.u64 t, %1; cvt.u32.u64 %0, t; }" : "=r"(a) : "l"(p));
    return a;
}

// ---- launch 0: classify+publish, degree count (blocks 0..1023), x@W (1024..3071) ----
__global__ void k_deg_xw(const void* p0, const void* p1, const void* p2, const void* p3,
                         int s0, int s1, int s2, int s3) {
    __shared__ float sW[D * D];
    Cls c = do_classify(p0, p1, p2, p3, s0, s1, s2, s3);
    int blk = blockIdx.x, tid = threadIdx.x;
    if (blk == 0 && tid == 0) {
        gp_x = c.x; gp_ei = c.ei; gp_W = c.W; gp_b = c.b; g_E = c.E; g_ei32 = c.ei32;
        __threadfence();
    }
    if (blk < 1024) {
        int e = blk * 256 + tid;
        if (e < c.E && e < EMAX) {
            int dst = fetch_idx(c.ei, c.E + e, c.ei32);
            if ((unsigned)dst < (unsigned)N_NODES) atomicAdd(&g_deg[dst], 1.0f);
        }
        return;
    }
    for (int i = tid; i < D * D; i += 256) sW[i] = c.W[i];
    __syncthreads();
    int row = (blk - 1024) * 4 + (tid >> 6);
    int col = tid & 63;
    const float* xr = c.x + row * D;
    float acc = 0.0f;
#pragma unroll
    for (int k = 0; k < D; k++) acc += xr[k] * sW[k * D + col];
    g_h[row * D + col] = acc;
}

// ---- launch 1: edge scatter (warp per edge) into zeroed g_agg ----
__global__ void k_scatter() {
    const void* ei = gp_ei;
    int E = g_E, ei32 = g_ei32;
    int gw = (blockIdx.x * blockDim.x + threadIdx.x) >> 5;
    int lane = threadIdx.x & 31;
    if (gw >= E || gw >= EMAX) return;
    int src = fetch_idx(ei, gw, ei32);
    int dst = fetch_idx(ei, E + gw, ei32);
    if ((unsigned)src >= (unsigned)N_NODES) return;
    if ((unsigned)dst >= (unsigned)N_NODES) return;
    float norm = rsqrtf(g_deg[src] + 1.0f) * rsqrtf(g_deg[dst] + 1.0f);  // +1 self-loop
    float2 v = ((const float2*)(g_h + src * D))[lane];
    atomicAdd(&g_agg[dst * D + lane * 2],     norm * v.x);
    atomicAdd(&g_agg[dst * D + lane * 2 + 1], norm * v.y);
}

// ---- launch 2: self-term + bias + relu + fp16 pack ----
__global__ void k_pack() {
    const float* __restrict__ b = gp_b;
    int idx = blockIdx.x * blockDim.x + threadIdx.x;
    if (idx >= N_NODES * D) return;
    int row = idx >> 6, col = idx & 63;
    float self = g_h[idx] / (g_deg[row] + 1.0f);   // dinv^2 * h
    float v = g_agg[idx] + self + b[col];
    v = v > 0.0f ? v : 0.0f;
    g_P[idx] = __float2half_rn(v);
}

// ---- launch 3: C = P @ P^T via mma.sync fp16, symmetric upper-tri tiles ----
// smem tile: 128 rows x 128 B (64 fp16), 8 16B-chunks/row, XOR row swizzle.
#define PROW_BYTES 128
#define PTILE_BYTES (128 * PROW_BYTES)      // 16384
#define TSTRIDE 132
#define SMEM_TOTAL 34816                     // max(2*16KB tiles, 64*132*4 B transpose)
#define CLEAN_CTAS 2016
#define CLEAN_WORDS (N_NODES * D + N_NODES)
#define WORDS_PER_CTA ((CLEAN_WORDS + CLEAN_CTAS - 1) / CLEAN_CTAS)

__device__ __forceinline__ uint32_t psw(int row, int chunk) {
    return (uint32_t)(row * PROW_BYTES + ((chunk ^ (row & 7)) << 4));
}

#define LDSM_X4(r0, r1, r2, r3, a) \
    asm volatile("ldmatrix.sync.aligned.m8n8.x4.shared.b16 {%0,%1,%2,%3}, [%4];" \
        : "=r"(r0), "=r"(r1), "=r"(r2), "=r"(r3) : "r"(a))

#define MMA_16816_F16(d, a, b) \
    asm volatile("mma.sync.aligned.m16n8k16.row.col.f32.f16.f16.f32 " \
        "{%0,%1,%2,%3}, {%4,%5,%6,%7}, {%8,%9}, {%0,%1,%2,%3};" \
        : "+f"((d)[0]), "+f"((d)[1]), "+f"((d)[2]), "+f"((d)[3]) \
        : "r"((a)[0]), "r"((a)[1]), "r"((a)[2]), "r"((a)[3]), "r"((b)[0]), "r"((b)[1]))

#define CP_ASYNC_16(smem_addr, gptr) \
    asm volatile("cp.async.cg.shared.global [%0], [%1], 16;" :: "r"(smem_addr), "l"(gptr) : "memory")

__global__ void __launch_bounds__(256, 2) k_gemm_mma(float* __restrict__ C) {
    int bi = blockIdx.y, bj = blockIdx.x;
    int tid = threadIdx.x;

    if (bj < bi) {
        // idle lower-triangle CTA: re-zero g_agg/g_deg for the next graph replay
        int cid = bi * (bi - 1) / 2 + bj;
        int w0 = cid * WORDS_PER_CTA;
        for (int k = tid; k < WORDS_PER_CTA; k += 256) {
            int w = w0 + k;
            if (w < N_NODES * D) g_agg[w] = 0.0f;
            else if (w < CLEAN_WORDS) g_deg[w - N_NODES * D] = 0.0f;
        }
        return;
    }

    extern __shared__ char smem[];
    char* sA = smem;
    char* sB = smem + PTILE_BYTES;
    uint32_t sA_u = smem_u32(sA);
    uint32_t sB_u = smem_u32(sB);

    int wid = tid >> 5, lane = tid & 31;
    int warp_m = wid >> 1;        // 0..3 -> 32-row slice
    int warp_n = wid & 1;         // 0..1 -> 64-col slice

    const char* gA = (const char*)(g_P + bi * 128 * D);
    const char* gB = (const char*)(g_P + bj * 128 * D);

    // load both 16KB tiles: 1024 chunks each, 4 iters x 256 threads
#pragma unroll
    for (int it = 0; it < 4; it++) {
        int q = it * 256 + tid;           // 0..1023
        int row = q >> 3, chunk = q & 7;
        uint32_t off = psw(row, chunk);
        CP_ASYNC_16(sA_u + off, gA + q * 16);
        CP_ASYNC_16(sB_u + off, gB + q * 16);
    }
    asm volatile("cp.async.commit_group;" ::: "memory");
    asm volatile("cp.async.wait_group 0;" ::: "memory");
    __syncthreads();

    int a_row_in16 = (lane & 7) | (lane & 8);
    int a_csub = lane >> 4;
    int b_row_in16 = (lane & 7) | ((lane >> 1) & 8);
    int b_csub = (lane >> 3) & 1;
    int a_row0 = warp_m * 32 + a_row_in16;
    int b_row0 = warp_n * 64 + b_row_in16;

    float acc[2][8][4];
#pragma unroll
    for (int mi = 0; mi < 2; mi++)
#pragma unroll
        for (int ni = 0; ni < 8; ni++)
#pragma unroll
            for (int v = 0; v < 4; v++) acc[mi][ni][v] = 0.0f;

#pragma unroll
    for (int s = 0; s < 4; s++) {
        int kc = s * 2;

        uint32_t a[2][4];
#pragma unroll
        for (int mi = 0; mi < 2; mi++)
            LDSM_X4(a[mi][0], a[mi][1], a[mi][2], a[mi][3],
                    sA_u + psw(a_row0 + mi * 16, kc + a_csub));

        uint32_t b[4][4];
#pragma unroll
        for (int nt = 0; nt < 4; nt++)
            LDSM_X4(b[nt][0], b[nt][1], b[nt][2], b[nt][3],
                    sB_u + psw(b_row0 + nt * 16, kc + b_csub));

#pragma unroll
        for (int mi = 0; mi < 2; mi++)
#pragma unroll
            for (int ni = 0; ni < 8; ni++) {
                uint32_t bb[2];
                bb[0] = b[ni >> 1][(ni & 1) * 2];
                bb[1] = b[ni >> 1][(ni & 1) * 2 + 1];
                MMA_16816_F16(acc[mi][ni], a[mi], bb);
            }
    }

    // ---- epilogue 1: direct store of C[bi, bj] ----
    int gr = lane >> 2, gc = (lane & 3) * 2;
#pragma unroll
    for (int mi = 0; mi < 2; mi++) {
        int row0 = bi * 128 + warp_m * 32 + mi * 16 + gr;
#pragma unroll
        for (int ni = 0; ni < 8; ni++) {
            int col = bj * 128 + warp_n * 64 + ni * 8 + gc;
            float* pp0 = C + (long long)row0 * NT + col;
            float* pp1 = pp0 + 8LL * NT;
            *(float2*)pp0 = make_float2(acc[mi][ni][0], acc[mi][ni][1]);
            *(float2*)pp1 = make_float2(acc[mi][ni][2], acc[mi][ni][3]);
        }
    }

    // ---- epilogue 2: transposed store of C[bj, bi], two 64-col passes ----
    if (bi == bj) return;
    float* sT = (float*)smem;   // 64 x TSTRIDE fp32 = 33792 B (tiles dead now)
#pragma unroll
    for (int p = 0; p < 2; p++) {
        __syncthreads();
        if (warp_n == p) {
#pragma unroll
            for (int mi = 0; mi < 2; mi++) {
                int lr = warp_m * 32 + mi * 16 + gr;
#pragma unroll
                for (int ni = 0; ni < 8; ni++) {
                    int lcl = ni * 8 + gc;        // 0..63 within this pass
                    sT[lcl * TSTRIDE + lr]           = acc[mi][ni][0];
                    sT[(lcl + 1) * TSTRIDE + lr]     = acc[mi][ni][1];
                    sT[lcl * TSTRIDE + lr + 8]       = acc[mi][ni][2];
                    sT[(lcl + 1) * TSTRIDE + lr + 8] = acc[mi][ni][3];
                }
            }
        }
        __syncthreads();
        // copy out 64 transposed rows x 128 cols, coalesced
        int r = tid >> 2, q = tid & 3;      // r: 0..63, q: 32-float quarter
        const float* srow = sT + r * TSTRIDE + q * 32;
        float* drow = C + (long long)(bj * 128 + p * 64 + r) * NT + bi * 128 + q * 32;
#pragma unroll
        for (int k = 0; k < 8; k++) {
            float4 v = *(const float4*)(srow + k * 4);
            *(float4*)(drow + k * 4) = v;
        }
    }
}

extern "C" void kernel_launch(void* const* d_in, const int* in_sizes, int n_in,
                              void* d_out, int out_size) {
    float* out = (float*)d_out;

    const void* p0 = n_in > 0 ? d_in[0] : nullptr;
    const void* p1 = n_in > 1 ? d_in[1] : nullptr;
    const void* p2 = n_in > 2 ? d_in[2] : nullptr;
    const void* p3 = n_in > 3 ? d_in[3] : nullptr;
    int s0 = n_in > 0 ? in_sizes[0] : 0;
    int s1 = n_in > 1 ? in_sizes[1] : 0;
    int s2 = n_in > 2 ? in_sizes[2] : 0;
    int s3 = n_in > 3 ? in_sizes[3] : 0;

    static bool attr_set = false;
    if (!attr_set) {
        cudaFuncSetAttribute(k_gemm_mma, cudaFuncAttributeMaxDynamicSharedMemorySize, SMEM_TOTAL);
        attr_set = true;
    }

    // launch 0: classify/publish + degree count + x@W
    k_deg_xw<<<3072, 256>>>(p0, p1, p2, p3, s0, s1, s2, s3);
    // launch 1: edge scatter, warp per edge
    k_scatter<<<(EMAX + 7) / 8, 256>>>();
    // launch 2: self term + bias + relu + fp16 pack
    k_pack<<<(N_NODES * D + 255) / 256, 256>>>();
    // launch 3: GEMM (ncu captures this index)
    dim3 grid(NT / 128, NT / 128);
    k_gemm_mma<<<grid, 256, SMEM_TOTAL>>>(out);
}

// round 11
// speedup vs baseline: 1.2927x; 1.1633x over previous
#include <cuda_runtime.h>
#include <cuda_fp16.h>
#include <math.h>
#include <stdint.h>

#define N_NODES 8192
#define D 64
#define NT 8192
#define EMAX 262144

// ---------------- scratch (no allocations allowed) ----------------
// Invariant: g_deg and g_agg are ZERO at entry (zero-init at load; re-zeroed
// by the GEMM's idle lower-triangle CTAs every call).
__device__ float g_deg[N_NODES];
__device__ float g_h[N_NODES * D];     // x @ W
__device__ float g_agg[N_NODES * D];   // neighbor-sum (excl. self term)
__device__ __half g_P[N_NODES * D];    // fp16(relu(gcn)) — both GEMM operands

struct Cls {
    const float* x;
    const void*  ei;
    const float* W;
    const float* b;
    int E;
    int ei32;
};

// Published by launch 0 (block 0) for later launches.
__device__ const float* gp_x;
__device__ const void*  gp_ei;
__device__ const float* gp_W;
__device__ const float* gp_b;
__device__ int          g_E;
__device__ int          g_ei32;

__device__ __forceinline__ bool rok64(const long long* p, int n) {
    int st = n >> 3;
    long long v[8];
#pragma unroll
    for (int k = 0; k < 8; k++) v[k] = p[k * st];
    bool ok = true;
#pragma unroll
    for (int k = 0; k < 8; k++) ok &= (v[k] >= 0 && v[k] < N_NODES);
    return ok;
}
__device__ __forceinline__ bool rok32(const int* p, int n) {
    int st = n >> 3;
    int v[8];
#pragma unroll
    for (int k = 0; k < 8; k++) v[k] = p[k * st];
    bool ok = true;
#pragma unroll
    for (int k = 0; k < 8; k++) ok &= (v[k] >= 0 && v[k] < N_NODES);
    return ok;
}

__device__ Cls do_classify(const void* p0, const void* p1, const void* p2, const void* p3,
                           int s0, int s1, int s2, int s3) {
    Cls c; c.x = nullptr; c.ei = nullptr; c.W = nullptr; c.b = nullptr; c.E = 0; c.ei32 = 1;
    const void* ps[4] = {p0, p1, p2, p3};
    int ss[4] = {s0, s1, s2, s3};
    int big[2]; int nb = 0;
#pragma unroll
    for (int j = 0; j < 4; j++) {
        if (ss[j] == D) c.b = (const float*)ps[j];
        else if (ss[j] == D * D) c.W = (const float*)ps[j];
        else if (nb < 2) big[nb++] = j;
    }
#pragma unroll
    for (int k = 0; k < 2; k++) {
        const void* cand = ps[big[k]];
        int n = ss[big[k]];
        const void* other = ps[big[1 - k]];
        if (rok64((const long long*)cand, n)) {
            c.ei = cand; c.ei32 = 0; c.E = n / 2; c.x = (const float*)other; return c;
        }
        if (rok32((const int*)cand, n)) {
            c.ei = cand; c.ei32 = 1; c.E = n / 2; c.x = (const float*)other; return c;
        }
    }
    c.ei = ps[big[1]]; c.ei32 = 1; c.E = ss[big[1]] / 2;
    c.x = (const float*)ps[big[0]];
    return c;
}

__device__ __forceinline__ int fetch_idx(const void* ei, int i, int ei32) {
    if (ei32) return ((const int*)ei)[i];
    return (int)((const long long*)ei)[i];
}

__device__ __forceinline__ uint32_t smem_u32(const void* p) {
    uint32_t a;
    asm("{ .reg .u64 t; cvta.to.shared.u64 t, %1; cvt.u32.u64 %0, t; }" : "=r"(a) : "l"(p));
    return a;
}

// ---- launch 0: classify+publish, deg count (blocks 0..1023), x@W (1024..1279) ----
__global__ void k_deg_xw(const void* p0, const void* p1, const void* p2, const void* p3,
                         int s0, int s1, int s2, int s3) {
    __shared__ float sW[D * D];
    Cls c = do_classify(p0, p1, p2, p3, s0, s1, s2, s3);
    int blk = blockIdx.x, tid = threadIdx.x;
    if (blk == 0 && tid == 0) {
        gp_x = c.x; gp_ei = c.ei; gp_W = c.W; gp_b = c.b; g_E = c.E; g_ei32 = c.ei32;
        __threadfence();
    }
    if (blk < 1024) {
        int e = blk * 256 + tid;
        if (e < c.E && e < EMAX) {
            int dst = fetch_idx(c.ei, c.E + e, c.ei32);
            if ((unsigned)dst < (unsigned)N_NODES) atomicAdd(&g_deg[dst], 1.0f);
        }
        return;
    }
    // x @ W: 256 blocks x 32 rows each (cuts W re-load traffic 8x)
    for (int i = tid; i < D * D; i += 256) sW[i] = c.W[i];
    __syncthreads();
    int base = (blk - 1024) * 32 + (tid >> 6) * 8;   // 8 rows per thread group
    int col = tid & 63;
#pragma unroll
    for (int rr = 0; rr < 8; rr++) {
        int row = base + rr;
        const float* xr = c.x + row * D;
        float acc = 0.0f;
#pragma unroll
        for (int k = 0; k < D; k++) acc += xr[k] * sW[k * D + col];
        g_h[row * D + col] = acc;
    }
}

// ---- launch 1: edge scatter (warp per edge) into zeroed g_agg ----
__global__ void k_scatter() {
    const void* ei = gp_ei;
    int E = g_E, ei32 = g_ei32;
    int gw = (blockIdx.x * blockDim.x + threadIdx.x) >> 5;
    int lane = threadIdx.x & 31;
    if (gw >= E || gw >= EMAX) return;
    int src = fetch_idx(ei, gw, ei32);
    int dst = fetch_idx(ei, E + gw, ei32);
    if ((unsigned)src >= (unsigned)N_NODES) return;
    if ((unsigned)dst >= (unsigned)N_NODES) return;
    float norm = rsqrtf(g_deg[src] + 1.0f) * rsqrtf(g_deg[dst] + 1.0f);  // +1 self-loop
    float2 v = ((const float2*)(g_h + src * D))[lane];
    atomicAdd(&g_agg[dst * D + lane * 2],     norm * v.x);
    atomicAdd(&g_agg[dst * D + lane * 2 + 1], norm * v.y);
}

// ---- launch 2: self-term + bias + relu + fp16 pack ----
__global__ void k_pack() {
    const float* __restrict__ b = gp_b;
    int idx = blockIdx.x * blockDim.x + threadIdx.x;
    if (idx >= N_NODES * D) return;
    int row = idx >> 6, col = idx & 63;
    float self = g_h[idx] / (g_deg[row] + 1.0f);   // dinv^2 * h
    float v = g_agg[idx] + self + b[col];
    v = v > 0.0f ? v : 0.0f;
    g_P[idx] = __float2half_rn(v);
}

// ---- launch 3: C = P @ P^T via mma.sync fp16, symmetric upper-tri tiles ----
// smem tile: 128 rows x 128 B (64 fp16), 8 16B-chunks/row, XOR row swizzle.
#define PROW_BYTES 128
#define PTILE_BYTES (128 * PROW_BYTES)      // 16384
#define TSTRIDE 132
#define SMEM_TOTAL 34816                     // max(2*16KB tiles, 64*132*4 stage)
#define CLEAN_CTAS 2016
#define CLEAN_WORDS (N_NODES * D + N_NODES)
#define WORDS_PER_CTA ((CLEAN_WORDS + CLEAN_CTAS - 1) / CLEAN_CTAS)

__device__ __forceinline__ uint32_t psw(int row, int chunk) {
    return (uint32_t)(row * PROW_BYTES + ((chunk ^ (row & 7)) << 4));
}

#define LDSM_X4(r0, r1, r2, r3, a) \
    asm volatile("ldmatrix.sync.aligned.m8n8.x4.shared.b16 {%0,%1,%2,%3}, [%4];" \
        : "=r"(r0), "=r"(r1), "=r"(r2), "=r"(r3) : "r"(a))

#define MMA_16816_F16(d, a, b) \
    asm volatile("mma.sync.aligned.m16n8k16.row.col.f32.f16.f16.f32 " \
        "{%0,%1,%2,%3}, {%4,%5,%6,%7}, {%8,%9}, {%0,%1,%2,%3};" \
        : "+f"((d)[0]), "+f"((d)[1]), "+f"((d)[2]), "+f"((d)[3]) \
        : "r"((a)[0]), "r"((a)[1]), "r"((a)[2]), "r"((a)[3]), "r"((b)[0]), "r"((b)[1]))

#define CP_ASYNC_16(smem_addr, gptr) \
    asm volatile("cp.async.cg.shared.global [%0], [%1], 16;" :: "r"(smem_addr), "l"(gptr) : "memory")

__global__ void __launch_bounds__(256, 2) k_gemm_mma(float* __restrict__ C) {
    int bi = blockIdx.y, bj = blockIdx.x;
    int tid = threadIdx.x;

    if (bj < bi) {
        // idle lower-triangle CTA: re-zero g_agg/g_deg for the next graph replay
        int cid = bi * (bi - 1) / 2 + bj;
        int w0 = cid * WORDS_PER_CTA;
        for (int k = tid; k < WORDS_PER_CTA; k += 256) {
            int w = w0 + k;
            if (w < N_NODES * D) g_agg[w] = 0.0f;
            else if (w < CLEAN_WORDS) g_deg[w - N_NODES * D] = 0.0f;
        }
        return;
    }

    extern __shared__ char smem[];
    char* sA = smem;
    char* sB = smem + PTILE_BYTES;
    uint32_t sA_u = smem_u32(sA);
    uint32_t sB_u = smem_u32(sB);

    int wid = tid >> 5, lane = tid & 31;
    int warp_m = wid >> 1;        // 0..3 -> 32-row slice
    int warp_n = wid & 1;         // 0..1 -> 64-col slice

    const char* gA = (const char*)(g_P + bi * 128 * D);
    const char* gB = (const char*)(g_P + bj * 128 * D);

#pragma unroll
    for (int it = 0; it < 4; it++) {
        int q = it * 256 + tid;           // 0..1023
        int row = q >> 3, chunk = q & 7;
        uint32_t off = psw(row, chunk);
        CP_ASYNC_16(sA_u + off, gA + q * 16);
        CP_ASYNC_16(sB_u + off, gB + q * 16);
    }
    asm volatile("cp.async.commit_group;" ::: "memory");
    asm volatile("cp.async.wait_group 0;" ::: "memory");
    __syncthreads();

    int a_row_in16 = (lane & 7) | (lane & 8);
    int a_csub = lane >> 4;
    int b_row_in16 = (lane & 7) | ((lane >> 1) & 8);
    int b_csub = (lane >> 3) & 1;
    int a_row0 = warp_m * 32 + a_row_in16;
    int b_row0 = warp_n * 64 + b_row_in16;

    float acc[2][8][4];
#pragma unroll
    for (int mi = 0; mi < 2; mi++)
#pragma unroll
        for (int ni = 0; ni < 8; ni++)
#pragma unroll
            for (int v = 0; v < 4; v++) acc[mi][ni][v] = 0.0f;

#pragma unroll
    for (int s = 0; s < 4; s++) {
        int kc = s * 2;

        uint32_t a[2][4];
#pragma unroll
        for (int mi = 0; mi < 2; mi++)
            LDSM_X4(a[mi][0], a[mi][1], a[mi][2], a[mi][3],
                    sA_u + psw(a_row0 + mi * 16, kc + a_csub));

        uint32_t b[4][4];
#pragma unroll
        for (int nt = 0; nt < 4; nt++)
            LDSM_X4(b[nt][0], b[nt][1], b[nt][2], b[nt][3],
                    sB_u + psw(b_row0 + nt * 16, kc + b_csub));

#pragma unroll
        for (int mi = 0; mi < 2; mi++)
#pragma unroll
            for (int ni = 0; ni < 8; ni++) {
                uint32_t bb[2];
                bb[0] = b[ni >> 1][(ni & 1) * 2];
                bb[1] = b[ni >> 1][(ni & 1) * 2 + 1];
                MMA_16816_F16(acc[mi][ni], a[mi], bb);
            }
    }

    int gr = lane >> 2, gc = (lane & 3) * 2;
    float* sS = (float*)smem;    // 64 x TSTRIDE fp32 staging (tiles dead after MMA)

    // ---- epilogue 1: staged store of C[bi, bj], two 64-row passes, float4 ----
#pragma unroll
    for (int p = 0; p < 2; p++) {
        __syncthreads();
        if ((warp_m >> 1) == p) {
            int lrb = (warp_m & 1) * 32;
#pragma unroll
            for (int mi = 0; mi < 2; mi++) {
#pragma unroll
                for (int ni = 0; ni < 8; ni++) {
                    int lr = lrb + mi * 16 + gr;
                    int lc = warp_n * 64 + ni * 8 + gc;
                    sS[lr * TSTRIDE + lc]           = acc[mi][ni][0];
                    sS[lr * TSTRIDE + lc + 1]       = acc[mi][ni][1];
                    sS[(lr + 8) * TSTRIDE + lc]     = acc[mi][ni][2];
                    sS[(lr + 8) * TSTRIDE + lc + 1] = acc[mi][ni][3];
                }
            }
        }
        __syncthreads();
#pragma unroll
        for (int k = 0; k < 8; k++) {
            int f = k * 256 + tid;           // float4 id 0..2047
            int row = f >> 5, c4 = f & 31;   // 32 float4 per 128-col row
            float4 v = *(const float4*)(sS + row * TSTRIDE + c4 * 4);
            *(float4*)(C + (long long)(bi * 128 + p * 64 + row) * NT + bj * 128 + c4 * 4) = v;
        }
    }

    // ---- epilogue 2: transposed store of C[bj, bi], two 64-col passes ----
    if (bi == bj) return;
#pragma unroll
    for (int p = 0; p < 2; p++) {
        __syncthreads();
        if (warp_n == p) {
#pragma unroll
            for (int mi = 0; mi < 2; mi++) {
                int lr = warp_m * 32 + mi * 16 + gr;
#pragma unroll
                for (int ni = 0; ni < 8; ni++) {
                    int lcl = ni * 8 + gc;        // 0..63 within this pass
                    sS[lcl * TSTRIDE + lr]           = acc[mi][ni][0];
                    sS[(lcl + 1) * TSTRIDE + lr]     = acc[mi][ni][1];
                    sS[lcl * TSTRIDE + lr + 8]       = acc[mi][ni][2];
                    sS[(lcl + 1) * TSTRIDE + lr + 8] = acc[mi][ni][3];
                }
            }
        }
        __syncthreads();
#pragma unroll
        for (int k = 0; k < 8; k++) {
            int f = k * 256 + tid;
            int row = f >> 5, c4 = f & 31;
            float4 v = *(const float4*)(sS + row * TSTRIDE + c4 * 4);
            *(float4*)(C + (long long)(bj * 128 + p * 64 + row) * NT + bi * 128 + c4 * 4) = v;
        }
    }
}

extern "C" void kernel_launch(void* const* d_in, const int* in_sizes, int n_in,
                              void* d_out, int out_size) {
    float* out = (float*)d_out;

    const void* p0 = n_in > 0 ? d_in[0] : nullptr;
    const void* p1 = n_in > 1 ? d_in[1] : nullptr;
    const void* p2 = n_in > 2 ? d_in[2] : nullptr;
    const void* p3 = n_in > 3 ? d_in[3] : nullptr;
    int s0 = n_in > 0 ? in_sizes[0] : 0;
    int s1 = n_in > 1 ? in_sizes[1] : 0;
    int s2 = n_in > 2 ? in_sizes[2] : 0;
    int s3 = n_in > 3 ? in_sizes[3] : 0;

    static bool attr_set = false;
    if (!attr_set) {
        cudaFuncSetAttribute(k_gemm_mma, cudaFuncAttributeMaxDynamicSharedMemorySize, SMEM_TOTAL);
        attr_set = true;
    }

    // launch 0: classify/publish + degree count (1024 blks) + x@W (256 blks)
    k_deg_xw<<<1280, 256>>>(p0, p1, p2, p3, s0, s1, s2, s3);
    // launch 1: edge scatter, warp per edge
    k_scatter<<<(EMAX + 7) / 8, 256>>>();
    // launch 2: self term + bias + relu + fp16 pack
    k_pack<<<(N_NODES * D + 255) / 256, 256>>>();
    // launch 3: GEMM (ncu captures this index)
    dim3 grid(NT / 128, NT / 128);
    k_gemm_mma<<<grid, 256, SMEM_TOTAL>>>(out);
}

// round 12
// speedup vs baseline: 1.4720x; 1.1387x over previous
#include <cuda_runtime.h>
#include <cuda_fp16.h>
#include <math.h>
#include <stdint.h>

#define N_NODES 8192
#define D 64
#define NT 8192
#define EMAX 262144

// ---------------- scratch (no allocations allowed) ----------------
// Invariant: g_deg and g_agg are ZERO at entry (zero-init at load; re-zeroed
// by the GEMM's idle lower-triangle CTAs every call).
__device__ float g_deg[N_NODES];
__device__ float g_h[N_NODES * D];     // x @ W
__device__ float g_agg[N_NODES * D];   // neighbor-sum (excl. self term)
__device__ __half g_P[N_NODES * D];    // fp16(relu(gcn)) — both GEMM operands

struct Cls {
    const float* x;
    const void*  ei;
    const float* W;
    const float* b;
    int E;
    int ei32;
};

// Published by launch 0 (block 0) for later launches.
__device__ const float* gp_x;
__device__ const void*  gp_ei;
__device__ const float* gp_W;
__device__ const float* gp_b;
__device__ int          g_E;
__device__ int          g_ei32;

__device__ __forceinline__ bool rok64(const long long* p, int n) {
    int st = n >> 3;
    long long v[8];
#pragma unroll
    for (int k = 0; k < 8; k++) v[k] = p[k * st];
    bool ok = true;
#pragma unroll
    for (int k = 0; k < 8; k++) ok &= (v[k] >= 0 && v[k] < N_NODES);
    return ok;
}
__device__ __forceinline__ bool rok32(const int* p, int n) {
    int st = n >> 3;
    int v[8];
#pragma unroll
    for (int k = 0; k < 8; k++) v[k] = p[k * st];
    bool ok = true;
#pragma unroll
    for (int k = 0; k < 8; k++) ok &= (v[k] >= 0 && v[k] < N_NODES);
    return ok;
}

__device__ Cls do_classify(const void* p0, const void* p1, const void* p2, const void* p3,
                           int s0, int s1, int s2, int s3) {
    Cls c; c.x = nullptr; c.ei = nullptr; c.W = nullptr; c.b = nullptr; c.E = 0; c.ei32 = 1;
    const void* ps[4] = {p0, p1, p2, p3};
    int ss[4] = {s0, s1, s2, s3};
    int big[2]; int nb = 0;
#pragma unroll
    for (int j = 0; j < 4; j++) {
        if (ss[j] == D) c.b = (const float*)ps[j];
        else if (ss[j] == D * D) c.W = (const float*)ps[j];
        else if (nb < 2) big[nb++] = j;
    }
#pragma unroll
    for (int k = 0; k < 2; k++) {
        const void* cand = ps[big[k]];
        int n = ss[big[k]];
        const void* other = ps[big[1 - k]];
        if (rok64((const long long*)cand, n)) {
            c.ei = cand; c.ei32 = 0; c.E = n / 2; c.x = (const float*)other; return c;
        }
        if (rok32((const int*)cand, n)) {
            c.ei = cand; c.ei32 = 1; c.E = n / 2; c.x = (const float*)other; return c;
        }
    }
    c.ei = ps[big[1]]; c.ei32 = 1; c.E = ss[big[1]] / 2;
    c.x = (const float*)ps[big[0]];
    return c;
}

__device__ __forceinline__ int fetch_idx(const void* ei, int i, int ei32) {
    if (ei32) return ((const int*)ei)[i];
    return (int)((const long long*)ei)[i];
}

__device__ __forceinline__ uint32_t smem_u32(const void* p) {
    uint32_t a;
    asm("{ .reg .u64 t; cvta.to.shared.u64 t, %1; cvt.u32.u64 %0, t; }" : "=r"(a) : "l"(p));
    return a;
}

// ---- launch 0: classify+publish, deg count (blocks 0..1023), x@W (1024..1279) ----
__global__ void k_deg_xw(const void* p0, const void* p1, const void* p2, const void* p3,
                         int s0, int s1, int s2, int s3) {
    __shared__ float sW[D * D];
    Cls c = do_classify(p0, p1, p2, p3, s0, s1, s2, s3);
    int blk = blockIdx.x, tid = threadIdx.x;
    if (blk == 0 && tid == 0) {
        gp_x = c.x; gp_ei = c.ei; gp_W = c.W; gp_b = c.b; g_E = c.E; g_ei32 = c.ei32;
        __threadfence();
    }
    if (blk < 1024) {
        int e = blk * 256 + tid;
        if (e < c.E && e < EMAX) {
            int dst = fetch_idx(c.ei, c.E + e, c.ei32);
            if ((unsigned)dst < (unsigned)N_NODES) atomicAdd(&g_deg[dst], 1.0f);
        }
        return;
    }
    // x @ W: 256 blocks x 32 rows each
    for (int i = tid; i < D * D; i += 256) sW[i] = c.W[i];
    __syncthreads();
    int base = (blk - 1024) * 32 + (tid >> 6) * 8;
    int col = tid & 63;
#pragma unroll
    for (int rr = 0; rr < 8; rr++) {
        int row = base + rr;
        const float* xr = c.x + row * D;
        float acc = 0.0f;
#pragma unroll
        for (int k = 0; k < D; k++) acc += xr[k] * sW[k * D + col];
        g_h[row * D + col] = acc;
    }
}

// ---- launch 1: edge scatter, 16 lanes/edge, float4 vector RED atomics ----
__global__ void k_scatter() {
    const void* ei = gp_ei;
    int E = g_E, ei32 = g_ei32;
    int gw = (blockIdx.x * blockDim.x + threadIdx.x) >> 5;
    int lane = threadIdx.x & 31;
    int e = gw * 2 + (lane >> 4);          // 2 edges per warp
    int l = lane & 15;                      // float4 index within 64-col row
    if (e >= E || e >= EMAX) return;
    int src = fetch_idx(ei, e, ei32);
    int dst = fetch_idx(ei, E + e, ei32);
    if ((unsigned)src >= (unsigned)N_NODES) return;
    if ((unsigned)dst >= (unsigned)N_NODES) return;
    float norm = rsqrtf(g_deg[src] + 1.0f) * rsqrtf(g_deg[dst] + 1.0f);  // +1 self-loop
    float4 v = ((const float4*)(g_h + src * D))[l];
    float* p = g_agg + dst * D + l * 4;
    asm volatile("red.global.add.v4.f32 [%0], {%1, %2, %3, %4};"
                 :: "l"(p), "f"(norm * v.x), "f"(norm * v.y),
                    "f"(norm * v.z), "f"(norm * v.w) : "memory");
}

// ---- launch 2: self-term + bias + relu + fp16 pack ----
__global__ void k_pack() {
    const float* __restrict__ b = gp_b;
    int idx = blockIdx.x * blockDim.x + threadIdx.x;
    if (idx >= N_NODES * D) return;
    int row = idx >> 6, col = idx & 63;
    float self = g_h[idx] / (g_deg[row] + 1.0f);   // dinv^2 * h
    float v = g_agg[idx] + self + b[col];
    v = v > 0.0f ? v : 0.0f;
    g_P[idx] = __float2half_rn(v);
}

// ---- launch 3: C = P @ P^T via mma.sync fp16, symmetric upper-tri tiles ----
// smem tiles: 128 rows x 128 B (64 fp16), 8 16B-chunks/row, XOR row swizzle.
// epilogue staging: full 128 x TSTRIDE fp32 buffer (tiles dead by then).
#define PROW_BYTES 128
#define PTILE_BYTES (128 * PROW_BYTES)      // 16384
#define TSTRIDE 132
#define SMEM_TOTAL (128 * TSTRIDE * 4)       // 67584 (> 2 tiles = 32768)
#define CLEAN_CTAS 2016
#define CLEAN_WORDS (N_NODES * D + N_NODES)
#define WORDS_PER_CTA ((CLEAN_WORDS + CLEAN_CTAS - 1) / CLEAN_CTAS)

__device__ __forceinline__ uint32_t psw(int row, int chunk) {
    return (uint32_t)(row * PROW_BYTES + ((chunk ^ (row & 7)) << 4));
}

#define LDSM_X4(r0, r1, r2, r3, a) \
    asm volatile("ldmatrix.sync.aligned.m8n8.x4.shared.b16 {%0,%1,%2,%3}, [%4];" \
        : "=r"(r0), "=r"(r1), "=r"(r2), "=r"(r3) : "r"(a))

#define MMA_16816_F16(d, a, b) \
    asm volatile("mma.sync.aligned.m16n8k16.row.col.f32.f16.f16.f32 " \
        "{%0,%1,%2,%3}, {%4,%5,%6,%7}, {%8,%9}, {%0,%1,%2,%3};" \
        : "+f"((d)[0]), "+f"((d)[1]), "+f"((d)[2]), "+f"((d)[3]) \
        : "r"((a)[0]), "r"((a)[1]), "r"((a)[2]), "r"((a)[3]), "r"((b)[0]), "r"((b)[1]))

#define CP_ASYNC_16(smem_addr, gptr) \
    asm volatile("cp.async.cg.shared.global [%0], [%1], 16;" :: "r"(smem_addr), "l"(gptr) : "memory")

__global__ void __launch_bounds__(256, 2) k_gemm_mma(float* __restrict__ C) {
    int bi = blockIdx.y, bj = blockIdx.x;
    int tid = threadIdx.x;

    if (bj < bi) {
        // idle lower-triangle CTA: re-zero g_agg/g_deg for the next graph replay
        int cid = bi * (bi - 1) / 2 + bj;
        int w0 = cid * WORDS_PER_CTA;
        for (int k = tid; k < WORDS_PER_CTA; k += 256) {
            int w = w0 + k;
            if (w < N_NODES * D) g_agg[w] = 0.0f;
            else if (w < CLEAN_WORDS) g_deg[w - N_NODES * D] = 0.0f;
        }
        return;
    }

    extern __shared__ char smem[];
    char* sA = smem;
    char* sB = smem + PTILE_BYTES;
    uint32_t sA_u = smem_u32(sA);
    uint32_t sB_u = smem_u32(sB);

    int wid = tid >> 5, lane = tid & 31;
    int warp_m = wid >> 1;        // 0..3 -> 32-row slice
    int warp_n = wid & 1;         // 0..1 -> 64-col slice

    const char* gA = (const char*)(g_P + bi * 128 * D);
    const char* gB = (const char*)(g_P + bj * 128 * D);

#pragma unroll
    for (int it = 0; it < 4; it++) {
        int q = it * 256 + tid;           // 0..1023
        int row = q >> 3, chunk = q & 7;
        uint32_t off = psw(row, chunk);
        CP_ASYNC_16(sA_u + off, gA + q * 16);
        CP_ASYNC_16(sB_u + off, gB + q * 16);
    }
    asm volatile("cp.async.commit_group;" ::: "memory");
    asm volatile("cp.async.wait_group 0;" ::: "memory");
    __syncthreads();

    int a_row_in16 = (lane & 7) | (lane & 8);
    int a_csub = lane >> 4;
    int b_row_in16 = (lane & 7) | ((lane >> 1) & 8);
    int b_csub = (lane >> 3) & 1;
    int a_row0 = warp_m * 32 + a_row_in16;
    int b_row0 = warp_n * 64 + b_row_in16;

    float acc[2][8][4];
#pragma unroll
    for (int mi = 0; mi < 2; mi++)
#pragma unroll
        for (int ni = 0; ni < 8; ni++)
#pragma unroll
            for (int v = 0; v < 4; v++) acc[mi][ni][v] = 0.0f;

#pragma unroll
    for (int s = 0; s < 4; s++) {
        int kc = s * 2;

        uint32_t a[2][4];
#pragma unroll
        for (int mi = 0; mi < 2; mi++)
            LDSM_X4(a[mi][0], a[mi][1], a[mi][2], a[mi][3],
                    sA_u + psw(a_row0 + mi * 16, kc + a_csub));

        uint32_t b[4][4];
#pragma unroll
        for (int nt = 0; nt < 4; nt++)
            LDSM_X4(b[nt][0], b[nt][1], b[nt][2], b[nt][3],
                    sB_u + psw(b_row0 + nt * 16, kc + b_csub));

#pragma unroll
        for (int mi = 0; mi < 2; mi++)
#pragma unroll
            for (int ni = 0; ni < 8; ni++) {
                uint32_t bb[2];
                bb[0] = b[ni >> 1][(ni & 1) * 2];
                bb[1] = b[ni >> 1][(ni & 1) * 2 + 1];
                MMA_16816_F16(acc[mi][ni], a[mi], bb);
            }
    }

    int gr = lane >> 2, gc = (lane & 3) * 2;
    float* sS = (float*)smem;    // 128 x TSTRIDE fp32 staging (tiles dead)

    // ---- epilogue 1: staged store of C[bi, bj], single pass, all warps ----
    __syncthreads();             // mainloop smem reads complete
#pragma unroll
    for (int mi = 0; mi < 2; mi++) {
#pragma unroll
        for (int ni = 0; ni < 8; ni++) {
            int lr = warp_m * 32 + mi * 16 + gr;
            int lc = warp_n * 64 + ni * 8 + gc;
            sS[lr * TSTRIDE + lc]           = acc[mi][ni][0];
            sS[lr * TSTRIDE + lc + 1]       = acc[mi][ni][1];
            sS[(lr + 8) * TSTRIDE + lc]     = acc[mi][ni][2];
            sS[(lr + 8) * TSTRIDE + lc + 1] = acc[mi][ni][3];
        }
    }
    __syncthreads();
#pragma unroll
    for (int k = 0; k < 16; k++) {
        int f = k * 256 + tid;           // float4 id 0..4095
        int row = f >> 5, c4 = f & 31;
        float4 v = *(const float4*)(sS + row * TSTRIDE + c4 * 4);
        *(float4*)(C + (long long)(bi * 128 + row) * NT + bj * 128 + c4 * 4) = v;
    }

    // ---- epilogue 2: transposed store of C[bj, bi], single pass ----
    if (bi == bj) return;
    __syncthreads();
#pragma unroll
    for (int mi = 0; mi < 2; mi++) {
#pragma unroll
        for (int ni = 0; ni < 8; ni++) {
            int lr = warp_m * 32 + mi * 16 + gr;
            int lc = warp_n * 64 + ni * 8 + gc;
            sS[lc * TSTRIDE + lr]           = acc[mi][ni][0];
            sS[(lc + 1) * TSTRIDE + lr]     = acc[mi][ni][1];
            sS[lc * TSTRIDE + lr + 8]       = acc[mi][ni][2];
            sS[(lc + 1) * TSTRIDE + lr + 8] = acc[mi][ni][3];
        }
    }
    __syncthreads();
#pragma unroll
    for (int k = 0; k < 16; k++) {
        int f = k * 256 + tid;
        int row = f >> 5, c4 = f & 31;
        float4 v = *(const float4*)(sS + row * TSTRIDE + c4 * 4);
        *(float4*)(C + (long long)(bj * 128 + row) * NT + bi * 128 + c4 * 4) = v;
    }
}

extern "C" void kernel_launch(void* const* d_in, const int* in_sizes, int n_in,
                              void* d_out, int out_size) {
    float* out = (float*)d_out;

    const void* p0 = n_in > 0 ? d_in[0] : nullptr;
    const void* p1 = n_in > 1 ? d_in[1] : nullptr;
    const void* p2 = n_in > 2 ? d_in[2] : nullptr;
    const void* p3 = n_in > 3 ? d_in[3] : nullptr;
    int s0 = n_in > 0 ? in_sizes[0] : 0;
    int s1 = n_in > 1 ? in_sizes[1] : 0;
    int s2 = n_in > 2 ? in_sizes[2] : 0;
    int s3 = n_in > 3 ? in_sizes[3] : 0;

    static bool attr_set = false;
    if (!attr_set) {
        cudaFuncSetAttribute(k_gemm_mma, cudaFuncAttributeMaxDynamicSharedMemorySize, SMEM_TOTAL);
        attr_set = true;
    }

    // launch 0: classify/publish + degree count (1024 blks) + x@W (256 blks)
    k_deg_xw<<<1280, 256>>>(p0, p1, p2, p3, s0, s1, s2, s3);
    // launch 1: edge scatter, 2 edges per warp, float4 RED
    k_scatter<<<EMAX / 16, 256>>>();
    // launch 2: self term + bias + relu + fp16 pack
    k_pack<<<(N_NODES * D + 255) / 256, 256>>>();
    // launch 3: GEMM (ncu captures this index)
    dim3 grid(NT / 128, NT / 128);
    k_gemm_mma<<<grid, 256, SMEM_TOTAL>>>(out);
}

// round 13
// speedup vs baseline: 1.5052x; 1.0226x over previous
#include <cuda_runtime.h>
#include <cuda_fp16.h>
#include <math.h>
#include <stdint.h>

#define N_NODES 8192
#define D 64
#define NT 8192
#define EMAX 262144

// ---------------- scratch (no allocations allowed) ----------------
// Invariant: g_deg is ZERO at entry (zero-init at load; re-zeroed by the
// GEMM's idle lower-triangle CTAs every call). Everything else is fully
// overwritten every call.
__device__ float g_deg[N_NODES];
__device__ float g_dinv[N_NODES];
__device__ int   g_off[N_NODES];
__device__ int   g_cur[N_NODES];
__device__ int   g_csr[EMAX];
__device__ float g_h[N_NODES * D];     // x @ W
__device__ __half g_P[N_NODES * D];    // fp16(relu(gcn)) — both GEMM operands

struct Cls {
    const float* x;
    const void*  ei;
    const float* W;
    const float* b;
    int E;
    int ei32;
};

// Published by launch 0 (block 0) for later launches.
__device__ const float* gp_x;
__device__ const void*  gp_ei;
__device__ const float* gp_W;
__device__ const float* gp_b;
__device__ int          g_E;
__device__ int          g_ei32;

__device__ __forceinline__ bool rok64(const long long* p, int n) {
    int st = n >> 3;
    long long v[8];
#pragma unroll
    for (int k = 0; k < 8; k++) v[k] = p[k * st];
    bool ok = true;
#pragma unroll
    for (int k = 0; k < 8; k++) ok &= (v[k] >= 0 && v[k] < N_NODES);
    return ok;
}
__device__ __forceinline__ bool rok32(const int* p, int n) {
    int st = n >> 3;
    int v[8];
#pragma unroll
    for (int k = 0; k < 8; k++) v[k] = p[k * st];
    bool ok = true;
#pragma unroll
    for (int k = 0; k < 8; k++) ok &= (v[k] >= 0 && v[k] < N_NODES);
    return ok;
}

__device__ Cls do_classify(const void* p0, const void* p1, const void* p2, const void* p3,
                           int s0, int s1, int s2, int s3) {
    Cls c; c.x = nullptr; c.ei = nullptr; c.W = nullptr; c.b = nullptr; c.E = 0; c.ei32 = 1;
    const void* ps[4] = {p0, p1, p2, p3};
    int ss[4] = {s0, s1, s2, s3};
    int big[2]; int nb = 0;
#pragma unroll
    for (int j = 0; j < 4; j++) {
        if (ss[j] == D) c.b = (const float*)ps[j];
        else if (ss[j] == D * D) c.W = (const float*)ps[j];
        else if (nb < 2) big[nb++] = j;
    }
#pragma unroll
    for (int k = 0; k < 2; k++) {
        const void* cand = ps[big[k]];
        int n = ss[big[k]];
        const void* other = ps[big[1 - k]];
        if (rok64((const long long*)cand, n)) {
            c.ei = cand; c.ei32 = 0; c.E = n / 2; c.x = (const float*)other; return c;
        }
        if (rok32((const int*)cand, n)) {
            c.ei = cand; c.ei32 = 1; c.E = n / 2; c.x = (const float*)other; return c;
        }
    }
    c.ei = ps[big[1]]; c.ei32 = 1; c.E = ss[big[1]] / 2;
    c.x = (const float*)ps[big[0]];
    return c;
}

__device__ __forceinline__ int fetch_idx(const void* ei, int i, int ei32) {
    if (ei32) return ((const int*)ei)[i];
    return (int)((const long long*)ei)[i];
}

__device__ __forceinline__ uint32_t smem_u32(const void* p) {
    uint32_t a;
    asm("{ .reg .u64 t; cvta.to.shared.u64 t, %1; cvt.u32.u64 %0, t; }" : "=r"(a) : "l"(p));
    return a;
}

// ---- launch 0: classify+publish, deg histogram (blocks 0..1023), x@W (1024..2047) ----
__global__ void k_deg_xw(const void* p0, const void* p1, const void* p2, const void* p3,
                         int s0, int s1, int s2, int s3) {
    Cls c = do_classify(p0, p1, p2, p3, s0, s1, s2, s3);
    int blk = blockIdx.x, tid = threadIdx.x;
    if (blk == 0 && tid == 0) {
        gp_x = c.x; gp_ei = c.ei; gp_W = c.W; gp_b = c.b; g_E = c.E; g_ei32 = c.ei32;
        __threadfence();
    }
    if (blk < 1024) {
        int e = blk * 256 + tid;
        if (e < c.E && e < EMAX) {
            int dst = fetch_idx(c.ei, c.E + e, c.ei32);
            if ((unsigned)dst < (unsigned)N_NODES) atomicAdd(&g_deg[dst], 1.0f);
        }
        return;
    }
    // x @ W: 1024 blocks x 8 rows, x staged in smem, 2 outputs/thread
    __shared__ float sW[D * D];
    __shared__ float sx[8 * D];
    int base = (blk - 1024) * 8;
#pragma unroll
    for (int i = 0; i < 4; i++)
        ((float4*)sW)[tid + i * 256] = ((const float4*)c.W)[tid + i * 256];
    if (tid < 128)
        ((float4*)sx)[tid] = ((const float4*)(c.x + base * D))[tid];
    __syncthreads();
    int col = tid & 63, rg = tid >> 6;   // rows rg and rg+4
    float acc0 = 0.0f, acc1 = 0.0f;
#pragma unroll
    for (int k = 0; k < D; k++) {
        float w = sW[k * D + col];
        acc0 = fmaf(sx[rg * D + k], w, acc0);
        acc1 = fmaf(sx[(rg + 4) * D + k], w, acc1);
    }
    g_h[(base + rg) * D + col] = acc0;
    g_h[(base + rg + 4) * D + col] = acc1;
}

// ---- launch 1: exclusive scan of degrees -> offsets/cursors, dinv ----
__global__ void k_scan() {
    __shared__ int ssum[1024];
    int t = threadIdx.x;
    int v[8]; int s = 0;
#pragma unroll
    for (int i = 0; i < 8; i++) {
        v[i] = (int)g_deg[t * 8 + i];
        s += v[i];
    }
    ssum[t] = s;
    __syncthreads();
    // Hillis-Steele inclusive scan
    for (int d = 1; d < 1024; d <<= 1) {
        int x = (t >= d) ? ssum[t - d] : 0;
        __syncthreads();
        ssum[t] += x;
        __syncthreads();
    }
    int run = ssum[t] - s;   // exclusive
#pragma unroll
    for (int i = 0; i < 8; i++) {
        int idx = t * 8 + i;
        g_off[idx] = run;
        g_cur[idx] = run;
        g_dinv[idx] = rsqrtf((float)v[i] + 1.0f);   // +1 self-loop
        run += v[i];
    }
}

// ---- launch 2: CSR edge-id scatter (int atomics on cursors) ----
__global__ void k_csr() {
    const void* ei = gp_ei;
    int E = g_E, ei32 = g_ei32;
    int e = blockIdx.x * blockDim.x + threadIdx.x;
    if (e >= E || e >= EMAX) return;
    int src = fetch_idx(ei, e, ei32);
    int dst = fetch_idx(ei, E + e, ei32);
    if ((unsigned)dst >= (unsigned)N_NODES) return;
    if ((unsigned)src >= (unsigned)N_NODES) src = 0;   // keep slot accounting consistent
    int slot = atomicAdd(&g_cur[dst], 1);
    g_csr[slot] = src;
}

// ---- launch 3: gather + self-term + bias + relu + fp16 pack, warp per node ----
__global__ void k_gather_pack() {
    const float* __restrict__ b = gp_b;
    int wid = threadIdx.x >> 5, lane = threadIdx.x & 31;
    int node = blockIdx.x * 8 + wid;
    int off = g_off[node];
    int n = (int)g_deg[node];
    float dv = g_dinv[node];

    float2 a0 = make_float2(0.0f, 0.0f), a1 = make_float2(0.0f, 0.0f);
    int e = 0;
    for (; e + 1 < n; e += 2) {
        int s0 = g_csr[off + e], s1 = g_csr[off + e + 1];
        float d0 = g_dinv[s0], d1 = g_dinv[s1];
        float2 v0 = ((const float2*)(g_h + s0 * D))[lane];
        float2 v1 = ((const float2*)(g_h + s1 * D))[lane];
        a0.x = fmaf(d0, v0.x, a0.x); a0.y = fmaf(d0, v0.y, a0.y);
        a1.x = fmaf(d1, v1.x, a1.x); a1.y = fmaf(d1, v1.y, a1.y);
    }
    if (e < n) {
        int s0 = g_csr[off + e];
        float d0 = g_dinv[s0];
        float2 v0 = ((const float2*)(g_h + s0 * D))[lane];
        a0.x = fmaf(d0, v0.x, a0.x); a0.y = fmaf(d0, v0.y, a0.y);
    }
    // self-loop term + norm + bias + relu
    float2 hv = ((const float2*)(g_h + node * D))[lane];
    float2 bb = ((const float2*)b)[lane];
    float ox = dv * (a0.x + a1.x + dv * hv.x) + bb.x;
    float oy = dv * (a0.y + a1.y + dv * hv.y) + bb.y;
    ox = ox > 0.0f ? ox : 0.0f;
    oy = oy > 0.0f ? oy : 0.0f;
    ((half2*)(g_P + node * D))[lane] = __floats2half2_rn(ox, oy);
}

// ---- launch 4: C = P @ P^T via mma.sync fp16, symmetric upper-tri tiles ----
#define PROW_BYTES 128
#define PTILE_BYTES (128 * PROW_BYTES)      // 16384
#define TSTRIDE 132
#define SMEM_TOTAL (128 * TSTRIDE * 4)       // 67584
#define CLEAN_CTAS 2016
#define CLEAN_WORDS N_NODES                  // only g_deg needs re-zeroing
#define WORDS_PER_CTA ((CLEAN_WORDS + CLEAN_CTAS - 1) / CLEAN_CTAS)

__device__ __forceinline__ uint32_t psw(int row, int chunk) {
    return (uint32_t)(row * PROW_BYTES + ((chunk ^ (row & 7)) << 4));
}

#define LDSM_X4(r0, r1, r2, r3, a) \
    asm volatile("ldmatrix.sync.aligned.m8n8.x4.shared.b16 {%0,%1,%2,%3}, [%4];" \
        : "=r"(r0), "=r"(r1), "=r"(r2), "=r"(r3) : "r"(a))

#define MMA_16816_F16(d, a, b) \
    asm volatile("mma.sync.aligned.m16n8k16.row.col.f32.f16.f16.f32 " \
        "{%0,%1,%2,%3}, {%4,%5,%6,%7}, {%8,%9}, {%0,%1,%2,%3};" \
        : "+f"((d)[0]), "+f"((d)[1]), "+f"((d)[2]), "+f"((d)[3]) \
        : "r"((a)[0]), "r"((a)[1]), "r"((a)[2]), "r"((a)[3]), "r"((b)[0]), "r"((b)[1]))

#define CP_ASYNC_16(smem_addr, gptr) \
    asm volatile("cp.async.cg.shared.global [%0], [%1], 16;" :: "r"(smem_addr), "l"(gptr) : "memory")

__global__ void __launch_bounds__(256, 2) k_gemm_mma(float* __restrict__ C) {
    int bi = blockIdx.y, bj = blockIdx.x;
    int tid = threadIdx.x;

    if (bj < bi) {
        // idle lower-triangle CTA: re-zero g_deg for the next graph replay
        int cid = bi * (bi - 1) / 2 + bj;
        int w0 = cid * WORDS_PER_CTA;
        for (int k = tid; k < WORDS_PER_CTA; k += 256) {
            int w = w0 + k;
            if (w < CLEAN_WORDS) g_deg[w] = 0.0f;
        }
        return;
    }

    extern __shared__ char smem[];
    char* sA = smem;
    char* sB = smem + PTILE_BYTES;
    uint32_t sA_u = smem_u32(sA);
    uint32_t sB_u = smem_u32(sB);

    int wid = tid >> 5, lane = tid & 31;
    int warp_m = wid >> 1;        // 0..3 -> 32-row slice
    int warp_n = wid & 1;         // 0..1 -> 64-col slice

    const char* gA = (const char*)(g_P + bi * 128 * D);
    const char* gB = (const char*)(g_P + bj * 128 * D);

#pragma unroll
    for (int it = 0; it < 4; it++) {
        int q = it * 256 + tid;           // 0..1023
        int row = q >> 3, chunk = q & 7;
        uint32_t off = psw(row, chunk);
        CP_ASYNC_16(sA_u + off, gA + q * 16);
        CP_ASYNC_16(sB_u + off, gB + q * 16);
    }
    asm volatile("cp.async.commit_group;" ::: "memory");
    asm volatile("cp.async.wait_group 0;" ::: "memory");
    __syncthreads();

    int a_row_in16 = (lane & 7) | (lane & 8);
    int a_csub = lane >> 4;
    int b_row_in16 = (lane & 7) | ((lane >> 1) & 8);
    int b_csub = (lane >> 3) & 1;
    int a_row0 = warp_m * 32 + a_row_in16;
    int b_row0 = warp_n * 64 + b_row_in16;

    float acc[2][8][4];
#pragma unroll
    for (int mi = 0; mi < 2; mi++)
#pragma unroll
        for (int ni = 0; ni < 8; ni++)
#pragma unroll
            for (int v = 0; v < 4; v++) acc[mi][ni][v] = 0.0f;

#pragma unroll
    for (int s = 0; s < 4; s++) {
        int kc = s * 2;

        uint32_t a[2][4];
#pragma unroll
        for (int mi = 0; mi < 2; mi++)
            LDSM_X4(a[mi][0], a[mi][1], a[mi][2], a[mi][3],
                    sA_u + psw(a_row0 + mi * 16, kc + a_csub));

        uint32_t b[4][4];
#pragma unroll
        for (int nt = 0; nt < 4; nt++)
            LDSM_X4(b[nt][0], b[nt][1], b[nt][2], b[nt][3],
                    sB_u + psw(b_row0 + nt * 16, kc + b_csub));

#pragma unroll
        for (int mi = 0; mi < 2; mi++)
#pragma unroll
            for (int ni = 0; ni < 8; ni++) {
                uint32_t bb[2];
                bb[0] = b[ni >> 1][(ni & 1) * 2];
                bb[1] = b[ni >> 1][(ni & 1) * 2 + 1];
                MMA_16816_F16(acc[mi][ni], a[mi], bb);
            }
    }

    int gr = lane >> 2, gc = (lane & 3) * 2;
    float* sS = (float*)smem;    // 128 x TSTRIDE fp32 staging (tiles dead)

    // ---- epilogue 1: staged store of C[bi, bj], single pass ----
    __syncthreads();
#pragma unroll
    for (int mi = 0; mi < 2; mi++) {
#pragma unroll
        for (int ni = 0; ni < 8; ni++) {
            int lr = warp_m * 32 + mi * 16 + gr;
            int lc = warp_n * 64 + ni * 8 + gc;
            sS[lr * TSTRIDE + lc]           = acc[mi][ni][0];
            sS[lr * TSTRIDE + lc + 1]       = acc[mi][ni][1];
            sS[(lr + 8) * TSTRIDE + lc]     = acc[mi][ni][2];
            sS[(lr + 8) * TSTRIDE + lc + 1] = acc[mi][ni][3];
        }
    }
    __syncthreads();
#pragma unroll
    for (int k = 0; k < 16; k++) {
        int f = k * 256 + tid;
        int row = f >> 5, c4 = f & 31;
        float4 v = *(const float4*)(sS + row * TSTRIDE + c4 * 4);
        *(float4*)(C + (long long)(bi * 128 + row) * NT + bj * 128 + c4 * 4) = v;
    }

    // ---- epilogue 2: transposed store of C[bj, bi], single pass ----
    if (bi == bj) return;
    __syncthreads();
#pragma unroll
    for (int mi = 0; mi < 2; mi++) {
#pragma unroll
        for (int ni = 0; ni < 8; ni++) {
            int lr = warp_m * 32 + mi * 16 + gr;
            int lc = warp_n * 64 + ni * 8 + gc;
            sS[lc * TSTRIDE + lr]           = acc[mi][ni][0];
            sS[(lc + 1) * TSTRIDE + lr]     = acc[mi][ni][1];
            sS[lc * TSTRIDE + lr + 8]       = acc[mi][ni][2];
            sS[(lc + 1) * TSTRIDE + lr + 8] = acc[mi][ni][3];
        }
    }
    __syncthreads();
#pragma unroll
    for (int k = 0; k < 16; k++) {
        int f = k * 256 + tid;
        int row = f >> 5, c4 = f & 31;
        float4 v = *(const float4*)(sS + row * TSTRIDE + c4 * 4);
        *(float4*)(C + (long long)(bj * 128 + row) * NT + bi * 128 + c4 * 4) = v;
    }
}

extern "C" void kernel_launch(void* const* d_in, const int* in_sizes, int n_in,
                              void* d_out, int out_size) {
    float* out = (float*)d_out;

    const void* p0 = n_in > 0 ? d_in[0] : nullptr;
    const void* p1 = n_in > 1 ? d_in[1] : nullptr;
    const void* p2 = n_in > 2 ? d_in[2] : nullptr;
    const void* p3 = n_in > 3 ? d_in[3] : nullptr;
    int s0 = n_in > 0 ? in_sizes[0] : 0;
    int s1 = n_in > 1 ? in_sizes[1] : 0;
    int s2 = n_in > 2 ? in_sizes[2] : 0;
    int s3 = n_in > 3 ? in_sizes[3] : 0;

    static bool attr_set = false;
    if (!attr_set) {
        cudaFuncSetAttribute(k_gemm_mma, cudaFuncAttributeMaxDynamicSharedMemorySize, SMEM_TOTAL);
        attr_set = true;
    }

    // launch 0: classify/publish + degree histogram (1024) + x@W (1024)
    k_deg_xw<<<2048, 256>>>(p0, p1, p2, p3, s0, s1, s2, s3);
    // launch 1: exclusive scan -> offsets/cursors + dinv
    k_scan<<<1, 1024>>>();
    // launch 2: CSR edge-id scatter
    k_csr<<<EMAX / 256, 256>>>();
    // launch 3: gather + pack (ncu captures this index)
    k_gather_pack<<<N_NODES / 8, 256>>>();
    // launch 4: GEMM
    dim3 grid(NT / 128, NT / 128);
    k_gemm_mma<<<grid, 256, SMEM_TOTAL>>>(out);
}

// round 14
// speedup vs baseline: 1.5109x; 1.0038x over previous
#include <cuda_runtime.h>
#include <cuda_fp16.h>
#include <math.h>
#include <stdint.h>

#define N_NODES 8192
#define D 64
#define NT 8192
#define EMAX 262144

// ---------------- scratch (no allocations allowed) ----------------
// Invariant: g_deg is ZERO at entry (zero-init at load; re-zeroed by the
// GEMM's idle lower-triangle CTAs every call).
__device__ float g_deg[N_NODES];
__device__ float g_dinv[N_NODES];
__device__ int   g_off[N_NODES];
__device__ int   g_cur[N_NODES];
__device__ int   g_csr[EMAX];
__device__ float g_h[N_NODES * D];     // x @ W
__device__ __half g_P[N_NODES * D];    // fp16(relu(gcn)) — both GEMM operands

struct Cls {
    const float* x;
    const void*  ei;
    const float* W;
    const float* b;
    int E;
    int ei32;
};

__device__ const float* gp_x;
__device__ const void*  gp_ei;
__device__ const float* gp_W;
__device__ const float* gp_b;
__device__ int          g_E;
__device__ int          g_ei32;

__device__ __forceinline__ bool rok64(const long long* p, int n) {
    int st = n >> 3;
    long long v[8];
#pragma unroll
    for (int k = 0; k < 8; k++) v[k] = p[k * st];
    bool ok = true;
#pragma unroll
    for (int k = 0; k < 8; k++) ok &= (v[k] >= 0 && v[k] < N_NODES);
    return ok;
}
__device__ __forceinline__ bool rok32(const int* p, int n) {
    int st = n >> 3;
    int v[8];
#pragma unroll
    for (int k = 0; k < 8; k++) v[k] = p[k * st];
    bool ok = true;
#pragma unroll
    for (int k = 0; k < 8; k++) ok &= (v[k] >= 0 && v[k] < N_NODES);
    return ok;
}

__device__ Cls do_classify(const void* p0, const void* p1, const void* p2, const void* p3,
                           int s0, int s1, int s2, int s3) {
    Cls c; c.x = nullptr; c.ei = nullptr; c.W = nullptr; c.b = nullptr; c.E = 0; c.ei32 = 1;
    const void* ps[4] = {p0, p1, p2, p3};
    int ss[4] = {s0, s1, s2, s3};
    int big[2]; int nb = 0;
#pragma unroll
    for (int j = 0; j < 4; j++) {
        if (ss[j] == D) c.b = (const float*)ps[j];
        else if (ss[j] == D * D) c.W = (const float*)ps[j];
        else if (nb < 2) big[nb++] = j;
    }
#pragma unroll
    for (int k = 0; k < 2; k++) {
        const void* cand = ps[big[k]];
        int n = ss[big[k]];
        const void* other = ps[big[1 - k]];
        if (rok64((const long long*)cand, n)) {
            c.ei = cand; c.ei32 = 0; c.E = n / 2; c.x = (const float*)other; return c;
        }
        if (rok32((const int*)cand, n)) {
            c.ei = cand; c.ei32 = 1; c.E = n / 2; c.x = (const float*)other; return c;
        }
    }
    c.ei = ps[big[1]]; c.ei32 = 1; c.E = ss[big[1]] / 2;
    c.x = (const float*)ps[big[0]];
    return c;
}

__device__ __forceinline__ int fetch_idx(const void* ei, int i, int ei32) {
    if (ei32) return ((const int*)ei)[i];
    return (int)((const long long*)ei)[i];
}

__device__ __forceinline__ uint32_t smem_u32(const void* p) {
    uint32_t a;
    asm("{ .reg .u64 t; cvta.to.shared.u64 t, %1; cvt.u32.u64 %0, t; }" : "=r"(a) : "l"(p));
    return a;
}

// ---- launch 0: classify+publish, deg histogram (blocks 0..1023), x@W (1024..2047) ----
__global__ void k_deg_xw(const void* p0, const void* p1, const void* p2, const void* p3,
                         int s0, int s1, int s2, int s3) {
    Cls c = do_classify(p0, p1, p2, p3, s0, s1, s2, s3);
    int blk = blockIdx.x, tid = threadIdx.x;
    if (blk == 0 && tid == 0) {
        gp_x = c.x; gp_ei = c.ei; gp_W = c.W; gp_b = c.b; g_E = c.E; g_ei32 = c.ei32;
        __threadfence();
    }
    if (blk < 1024) {
        int e = blk * 256 + tid;
        if (e < c.E && e < EMAX) {
            int dst = fetch_idx(c.ei, c.E + e, c.ei32);
            if ((unsigned)dst < (unsigned)N_NODES) atomicAdd(&g_deg[dst], 1.0f);
        }
        return;
    }
    // x @ W: 1024 blocks x 8 rows, x staged in smem, 2 outputs/thread
    __shared__ float sW[D * D];
    __shared__ float sx[8 * D];
    int base = (blk - 1024) * 8;
#pragma unroll
    for (int i = 0; i < 4; i++)
        ((float4*)sW)[tid + i * 256] = ((const float4*)c.W)[tid + i * 256];
    if (tid < 128)
        ((float4*)sx)[tid] = ((const float4*)(c.x + base * D))[tid];
    __syncthreads();
    int col = tid & 63, rg = tid >> 6;
    float acc0 = 0.0f, acc1 = 0.0f;
#pragma unroll
    for (int k = 0; k < D; k++) {
        float w = sW[k * D + col];
        acc0 = fmaf(sx[rg * D + k], w, acc0);
        acc1 = fmaf(sx[(rg + 4) * D + k], w, acc1);
    }
    g_h[(base + rg) * D + col] = acc0;
    g_h[(base + rg + 4) * D + col] = acc1;
}

// ---- launch 1: exclusive scan of degrees -> offsets/cursors, dinv ----
__global__ void k_scan() {
    __shared__ int ssum[1024];
    int t = threadIdx.x;
    int v[8]; int s = 0;
#pragma unroll
    for (int i = 0; i < 8; i++) {
        v[i] = (int)g_deg[t * 8 + i];
        s += v[i];
    }
    ssum[t] = s;
    __syncthreads();
    for (int d = 1; d < 1024; d <<= 1) {
        int x = (t >= d) ? ssum[t - d] : 0;
        __syncthreads();
        ssum[t] += x;
        __syncthreads();
    }
    int run = ssum[t] - s;   // exclusive
#pragma unroll
    for (int i = 0; i < 8; i++) {
        int idx = t * 8 + i;
        g_off[idx] = run;
        g_cur[idx] = run;
        g_dinv[idx] = rsqrtf((float)v[i] + 1.0f);   // +1 self-loop
        run += v[i];
    }
}

// ---- launch 2: CSR edge-id scatter (int atomics on cursors) ----
__global__ void k_csr() {
    const void* ei = gp_ei;
    int E = g_E, ei32 = g_ei32;
    int e = blockIdx.x * blockDim.x + threadIdx.x;
    if (e >= E || e >= EMAX) return;
    int src = fetch_idx(ei, e, ei32);
    int dst = fetch_idx(ei, E + e, ei32);
    if ((unsigned)dst >= (unsigned)N_NODES) return;
    if ((unsigned)src >= (unsigned)N_NODES) src = 0;
    int slot = atomicAdd(&g_cur[dst], 1);
    g_csr[slot] = src;
}

// ---- launch 3: gather + self-term + bias + relu + fp16 pack, warp per node ----
// One coalesced csr load per 32 edges (shuffle-broadcast), 4 independent
// accumulation chains to hide L2 latency.
__global__ void k_gather_pack() {
    const float* __restrict__ b = gp_b;
    int wid = threadIdx.x >> 5, lane = threadIdx.x & 31;
    int node = blockIdx.x * 8 + wid;
    int off = g_off[node];
    int n = (int)g_deg[node];
    float dv = g_dinv[node];

    float2 a0 = make_float2(0.f, 0.f), a1 = make_float2(0.f, 0.f);
    float2 a2 = make_float2(0.f, 0.f), a3 = make_float2(0.f, 0.f);

    for (int base = 0; base < n; base += 32) {
        int cnt = n - base; if (cnt > 32) cnt = 32;
        int idx = 0;
        if (lane < cnt) idx = g_csr[off + base + lane];
        int e = 0;
        for (; e + 4 <= cnt; e += 4) {
            int s0 = __shfl_sync(0xffffffffu, idx, e);
            int s1 = __shfl_sync(0xffffffffu, idx, e + 1);
            int s2 = __shfl_sync(0xffffffffu, idx, e + 2);
            int s3 = __shfl_sync(0xffffffffu, idx, e + 3);
            float d0 = g_dinv[s0], d1 = g_dinv[s1], d2 = g_dinv[s2], d3 = g_dinv[s3];
            float2 v0 = ((const float2*)(g_h + s0 * D))[lane];
            float2 v1 = ((const float2*)(g_h + s1 * D))[lane];
            float2 v2 = ((const float2*)(g_h + s2 * D))[lane];
            float2 v3 = ((const float2*)(g_h + s3 * D))[lane];
            a0.x = fmaf(d0, v0.x, a0.x); a0.y = fmaf(d0, v0.y, a0.y);
            a1.x = fmaf(d1, v1.x, a1.x); a1.y = fmaf(d1, v1.y, a1.y);
            a2.x = fmaf(d2, v2.x, a2.x); a2.y = fmaf(d2, v2.y, a2.y);
            a3.x = fmaf(d3, v3.x, a3.x); a3.y = fmaf(d3, v3.y, a3.y);
        }
        for (; e < cnt; e++) {
            int s0 = __shfl_sync(0xffffffffu, idx, e);
            float d0 = g_dinv[s0];
            float2 v0 = ((const float2*)(g_h + s0 * D))[lane];
            a0.x = fmaf(d0, v0.x, a0.x); a0.y = fmaf(d0, v0.y, a0.y);
        }
    }

    float2 hv = ((const float2*)(g_h + node * D))[lane];
    float2 bb = ((const float2*)b)[lane];
    float sx = a0.x + a1.x + a2.x + a3.x;
    float sy = a0.y + a1.y + a2.y + a3.y;
    float ox = dv * (sx + dv * hv.x) + bb.x;
    float oy = dv * (sy + dv * hv.y) + bb.y;
    ox = ox > 0.0f ? ox : 0.0f;
    oy = oy > 0.0f ? oy : 0.0f;
    ((half2*)(g_P + node * D))[lane] = __floats2half2_rn(ox, oy);
}

// ---- launch 4: C = P @ P^T via mma.sync fp16, symmetric upper-tri tiles ----
#define PROW_BYTES 128
#define PTILE_BYTES (128 * PROW_BYTES)      // 16384
#define TSTRIDE 132
#define SMEM_TOTAL (128 * TSTRIDE * 4)       // 67584
#define CLEAN_CTAS 2016
#define CLEAN_WORDS N_NODES
#define WORDS_PER_CTA ((CLEAN_WORDS + CLEAN_CTAS - 1) / CLEAN_CTAS)

__device__ __forceinline__ uint32_t psw(int row, int chunk) {
    return (uint32_t)(row * PROW_BYTES + ((chunk ^ (row & 7)) << 4));
}

#define LDSM_X4(r0, r1, r2, r3, a) \
    asm volatile("ldmatrix.sync.aligned.m8n8.x4.shared.b16 {%0,%1,%2,%3}, [%4];" \
        : "=r"(r0), "=r"(r1), "=r"(r2), "=r"(r3) : "r"(a))

#define MMA_16816_F16(d, a, b) \
    asm volatile("mma.sync.aligned.m16n8k16.row.col.f32.f16.f16.f32 " \
        "{%0,%1,%2,%3}, {%4,%5,%6,%7}, {%8,%9}, {%0,%1,%2,%3};" \
        : "+f"((d)[0]), "+f"((d)[1]), "+f"((d)[2]), "+f"((d)[3]) \
        : "r"((a)[0]), "r"((a)[1]), "r"((a)[2]), "r"((a)[3]), "r"((b)[0]), "r"((b)[1]))

#define CP_ASYNC_16(smem_addr, gptr) \
    asm volatile("cp.async.cg.shared.global [%0], [%1], 16;" :: "r"(smem_addr), "l"(gptr) : "memory")

__global__ void __launch_bounds__(256, 2) k_gemm_mma(float* __restrict__ C) {
    int bi = blockIdx.y, bj = blockIdx.x;
    int tid = threadIdx.x;

    if (bj < bi) {
        int cid = bi * (bi - 1) / 2 + bj;
        int w0 = cid * WORDS_PER_CTA;
        for (int k = tid; k < WORDS_PER_CTA; k += 256) {
            int w = w0 + k;
            if (w < CLEAN_WORDS) g_deg[w] = 0.0f;
        }
        return;
    }

    extern __shared__ char smem[];
    char* sA = smem;
    char* sB = smem + PTILE_BYTES;
    uint32_t sA_u = smem_u32(sA);
    uint32_t sB_u = smem_u32(sB);

    int wid = tid >> 5, lane = tid & 31;
    int warp_m = wid >> 1;
    int warp_n = wid & 1;

    const char* gA = (const char*)(g_P + bi * 128 * D);
    const char* gB = (const char*)(g_P + bj * 128 * D);

#pragma unroll
    for (int it = 0; it < 4; it++) {
        int q = it * 256 + tid;
        int row = q >> 3, chunk = q & 7;
        uint32_t off = psw(row, chunk);
        CP_ASYNC_16(sA_u + off, gA + q * 16);
        CP_ASYNC_16(sB_u + off, gB + q * 16);
    }
    asm volatile("cp.async.commit_group;" ::: "memory");
    asm volatile("cp.async.wait_group 0;" ::: "memory");
    __syncthreads();

    int a_row_in16 = (lane & 7) | (lane & 8);
    int a_csub = lane >> 4;
    int b_row_in16 = (lane & 7) | ((lane >> 1) & 8);
    int b_csub = (lane >> 3) & 1;
    int a_row0 = warp_m * 32 + a_row_in16;
    int b_row0 = warp_n * 64 + b_row_in16;

    float acc[2][8][4];
#pragma unroll
    for (int mi = 0; mi < 2; mi++)
#pragma unroll
        for (int ni = 0; ni < 8; ni++)
#pragma unroll
            for (int v = 0; v < 4; v++) acc[mi][ni][v] = 0.0f;

#pragma unroll
    for (int s = 0; s < 4; s++) {
        int kc = s * 2;

        uint32_t a[2][4];
#pragma unroll
        for (int mi = 0; mi < 2; mi++)
            LDSM_X4(a[mi][0], a[mi][1], a[mi][2], a[mi][3],
                    sA_u + psw(a_row0 + mi * 16, kc + a_csub));

        uint32_t b[4][4];
#pragma unroll
        for (int nt = 0; nt < 4; nt++)
            LDSM_X4(b[nt][0], b[nt][1], b[nt][2], b[nt][3],
                    sB_u + psw(b_row0 + nt * 16, kc + b_csub));

#pragma unroll
        for (int mi = 0; mi < 2; mi++)
#pragma unroll
            for (int ni = 0; ni < 8; ni++) {
                uint32_t bb[2];
                bb[0] = b[ni >> 1][(ni & 1) * 2];
                bb[1] = b[ni >> 1][(ni & 1) * 2 + 1];
                MMA_16816_F16(acc[mi][ni], a[mi], bb);
            }
    }

    int gr = lane >> 2, gc = (lane & 3) * 2;
    float* sS = (float*)smem;

    // ---- epilogue 1: staged store of C[bi, bj], single pass ----
    __syncthreads();
#pragma unroll
    for (int mi = 0; mi < 2; mi++) {
#pragma unroll
        for (int ni = 0; ni < 8; ni++) {
            int lr = warp_m * 32 + mi * 16 + gr;
            int lc = warp_n * 64 + ni * 8 + gc;
            sS[lr * TSTRIDE + lc]           = acc[mi][ni][0];
            sS[lr * TSTRIDE + lc + 1]       = acc[mi][ni][1];
            sS[(lr + 8) * TSTRIDE + lc]     = acc[mi][ni][2];
            sS[(lr + 8) * TSTRIDE + lc + 1] = acc[mi][ni][3];
        }
    }
    __syncthreads();
#pragma unroll
    for (int k = 0; k < 16; k++) {
        int f = k * 256 + tid;
        int row = f >> 5, c4 = f & 31;
        float4 v = *(const float4*)(sS + row * TSTRIDE + c4 * 4);
        *(float4*)(C + (long long)(bi * 128 + row) * NT + bj * 128 + c4 * 4) = v;
    }

    // ---- epilogue 2: transposed store of C[bj, bi], single pass ----
    if (bi == bj) return;
    __syncthreads();
#pragma unroll
    for (int mi = 0; mi < 2; mi++) {
#pragma unroll
        for (int ni = 0; ni < 8; ni++) {
            int lr = warp_m * 32 + mi * 16 + gr;
            int lc = warp_n * 64 + ni * 8 + gc;
            sS[lc * TSTRIDE + lr]           = acc[mi][ni][0];
            sS[(lc + 1) * TSTRIDE + lr]     = acc[mi][ni][1];
            sS[lc * TSTRIDE + lr + 8]       = acc[mi][ni][2];
            sS[(lc + 1) * TSTRIDE + lr + 8] = acc[mi][ni][3];
        }
    }
    __syncthreads();
#pragma unroll
    for (int k = 0; k < 16; k++) {
        int f = k * 256 + tid;
        int row = f >> 5, c4 = f & 31;
        float4 v = *(const float4*)(sS + row * TSTRIDE + c4 * 4);
        *(float4*)(C + (long long)(bj * 128 + row) * NT + bi * 128 + c4 * 4) = v;
    }
}

extern "C" void kernel_launch(void* const* d_in, const int* in_sizes, int n_in,
                              void* d_out, int out_size) {
    float* out = (float*)d_out;

    const void* p0 = n_in > 0 ? d_in[0] : nullptr;
    const void* p1 = n_in > 1 ? d_in[1] : nullptr;
    const void* p2 = n_in > 2 ? d_in[2] : nullptr;
    const void* p3 = n_in > 3 ? d_in[3] : nullptr;
    int s0 = n_in > 0 ? in_sizes[0] : 0;
    int s1 = n_in > 1 ? in_sizes[1] : 0;
    int s2 = n_in > 2 ? in_sizes[2] : 0;
    int s3 = n_in > 3 ? in_sizes[3] : 0;

    static bool attr_set = false;
    if (!attr_set) {
        cudaFuncSetAttribute(k_gemm_mma, cudaFuncAttributeMaxDynamicSharedMemorySize, SMEM_TOTAL);
        attr_set = true;
    }

    k_deg_xw<<<2048, 256>>>(p0, p1, p2, p3, s0, s1, s2, s3);
    k_scan<<<1, 1024>>>();
    k_csr<<<EMAX / 256, 256>>>();
    k_gather_pack<<<N_NODES / 8, 256>>>();
    dim3 grid(NT / 128, NT / 128);
    k_gemm_mma<<<grid, 256, SMEM_TOTAL>>>(out);
}